// round 5
// baseline (speedup 1.0000x reference)
#include <cuda_runtime.h>
#include <cuda_bf16.h>
#include <math.h>
#include <stdint.h>

#define Bc 128
#define Tc 32
#define Fc 2048
#define G3 6144
#define Hc 64
#define Nn 4096
#define KSPLIT 16
#define KCHUNK 128   // Fc / KSPLIT
#define KT 16
#define NKT (KCHUNK/KT)
#define NTILE 128
#define BPAD 130     // B dup-pair row stride (128 + 2 pad)

// ---- static scratch (no cudaMalloc allowed) ----
__device__ float g_Xs[Bc*Tc*Fc];
__device__ float g_Gi[(size_t)Bc*Tc*G3];
__device__ float g_H0[Bc*Tc*Fc];
__device__ float g_Emb[Bc*Tc*Fc];
__device__ float g_hz[Tc*Fc];
__device__ float g_P[(size_t)KSPLIT*Tc*G3];
__device__ float g_XN[Nn*Hc];
__device__ float g_XL[Nn*Hc];
__device__ float g_XR[Nn*Hc];
__device__ float g_G0[Nn*Hc];
__device__ float g_G1[Nn*Hc];
__device__ float g_FUS[Nn*2*Hc];
__device__ float g_PR[(size_t)Nn*2048];

// ---- packed f32x2 helpers ----
__device__ __forceinline__ unsigned long long pk2(float x){
    unsigned long long r; asm("mov.b64 %0,{%1,%1};" : "=l"(r) : "f"(x)); return r;
}
__device__ __forceinline__ unsigned long long pk2b(float x, float y){
    unsigned long long r; asm("mov.b64 %0,{%1,%2};" : "=l"(r) : "f"(x), "f"(y)); return r;
}
__device__ __forceinline__ void ffma2(unsigned long long& d, unsigned long long a, unsigned long long b){
    asm("fma.rn.f32x2 %0,%1,%2,%0;" : "+l"(d) : "l"(a), "l"(b));
}
__device__ __forceinline__ float2 up2(unsigned long long v){
    float2 r; asm("mov.b64 {%0,%1},%2;" : "=f"(r.x), "=f"(r.y) : "l"(v)); return r;
}

// ---- utility ----
__global__ void k_zero(float* p, int n){ int i=blockIdx.x*256+threadIdx.x; if(i<n) p[i]=0.f; }

__global__ void k_sanitize(const float* __restrict__ in, float* __restrict__ out, int n){
    int i = blockIdx.x*256 + threadIdx.x;
    if(i<n){
        float v = in[i];
        if (isnan(v)) v = 0.f;
        else if (isinf(v)) v = (v>0.f) ? 1.0f : -3.4028234663852886e38f;
        out[i] = v;
    }
}

// ---- big SGEMM: C[M,N] = A[M,K] @ B[N,K]^T (+bias), 128x128 tile, f32x2 ----
__global__ void __launch_bounds__(256) k_sgemm(const float* __restrict__ A,
                                               const float* __restrict__ Bm,
                                               const float* __restrict__ bias,
                                               float* __restrict__ C,
                                               int Ncols, int K)
{
    __shared__ float As[8][128];
    __shared__ float Bs[8][128];
    const int tid = threadIdx.x;
    const int tx = tid & 15, ty = tid >> 4;
    const int m0 = blockIdx.y*128, n0 = blockIdx.x*128;
    const int lr = tid >> 1, lc = (tid & 1)*4;
    const float* Ap = A + (size_t)(m0+lr)*K + lc;
    const float* Bp = Bm + (size_t)(n0+lr)*K + lc;

    unsigned long long acc[8][4];
    #pragma unroll
    for(int i=0;i<8;i++)
        #pragma unroll
        for(int j=0;j<4;j++) acc[i][j]=0ULL;

    for(int k0=0;k0<K;k0+=8){
        float4 av = *(const float4*)(Ap + k0);
        float4 bv = *(const float4*)(Bp + k0);
        __syncthreads();
        As[lc+0][lr]=av.x; As[lc+1][lr]=av.y; As[lc+2][lr]=av.z; As[lc+3][lr]=av.w;
        Bs[lc+0][lr]=bv.x; Bs[lc+1][lr]=bv.y; Bs[lc+2][lr]=bv.z; Bs[lc+3][lr]=bv.w;
        __syncthreads();
        #pragma unroll
        for(int k=0;k<8;k++){
            float4 a0 = *(const float4*)&As[k][ty*8];
            float4 a1 = *(const float4*)&As[k][ty*8+4];
            ulonglong2 b01 = *(const ulonglong2*)&Bs[k][tx*8];
            ulonglong2 b23 = *(const ulonglong2*)&Bs[k][tx*8+4];
            unsigned long long aa[8];
            aa[0]=pk2(a0.x); aa[1]=pk2(a0.y); aa[2]=pk2(a0.z); aa[3]=pk2(a0.w);
            aa[4]=pk2(a1.x); aa[5]=pk2(a1.y); aa[6]=pk2(a1.z); aa[7]=pk2(a1.w);
            #pragma unroll
            for(int i=0;i<8;i++){
                ffma2(acc[i][0], aa[i], b01.x);
                ffma2(acc[i][1], aa[i], b01.y);
                ffma2(acc[i][2], aa[i], b23.x);
                ffma2(acc[i][3], aa[i], b23.y);
            }
        }
    }
    #pragma unroll
    for(int i=0;i<8;i++){
        int row = m0 + ty*8 + i;
        #pragma unroll
        for(int j=0;j<4;j++){
            float2 v = up2(acc[i][j]);
            int col = n0 + tx*8 + j*2;
            float b0 = bias ? bias[col]   : 0.f;
            float b1 = bias ? bias[col+1] : 0.f;
            C[(size_t)row*Ncols + col]   = v.x + b0;
            C[(size_t)row*Ncols + col+1] = v.y + b1;
        }
    }
}

// ---- recurrent GEMM: P[ks][32][6144] partials of H[32,2048] @ W[6144,2048]^T ----
// tile M=32 x N=128, KCHUNK=128, KT=16 double-buffered.
// B is stored DUPLICATED in smem as (v,v) f32 pairs -> inner loop has zero movs:
//   per k: 8 FFMA2 + 1 LDS.128 (A row-pairs) + 2 LDS.128 (B dup) = 73% FMA mix.
// grid (48, 16) = 768 CTAs, block 256, thread tile 4 rows x 4 cols.
__global__ void __launch_bounds__(256) k_rgemm(const float* __restrict__ H,
                                               const float* __restrict__ W,
                                               float* __restrict__ P)
{
    __shared__ float As[2][KT][36];
    __shared__ unsigned long long Bd[2][KT][BPAD];
    const int tid = threadIdx.x;
    const int cg = tid & 31;        // 32 col groups x 4 cols
    const int rg = tid >> 5;        // 8 row groups x 4 rows
    const int n0 = blockIdx.x * NTILE;
    const int kbase = blockIdx.y * KCHUNK;

    // A loader mapping: threads 0..127, row=tid>>2, kq=tid&3
    const int a_row = tid >> 2, a_kq = tid & 3;
    // B loader mapping: col=tid>>1, kq2=tid&1 ; two float4 along k (k 0..7, 8..15)
    const int b_col = tid >> 1, b_kq = tid & 1;

    unsigned long long acc[2][4];
    #pragma unroll
    for(int i=0;i<2;i++)
        #pragma unroll
        for(int j=0;j<4;j++) acc[i][j]=0ULL;

    float4 stA; float4 stB0, stB1;

    // prologue: load ktile 0
    {
        const int gk = kbase;
        if(tid < 128) stA = *(const float4*)(H + (size_t)a_row*Fc + gk + a_kq*4);
        const float* wrow = W + (size_t)(n0 + b_col)*Fc + gk;
        stB0 = *(const float4*)(wrow + b_kq*4);
        stB1 = *(const float4*)(wrow + 8 + b_kq*4);
        if(tid < 128){
            As[0][a_kq*4+0][a_row]=stA.x; As[0][a_kq*4+1][a_row]=stA.y;
            As[0][a_kq*4+2][a_row]=stA.z; As[0][a_kq*4+3][a_row]=stA.w;
        }
        Bd[0][b_kq*4+0][b_col]=pk2(stB0.x); Bd[0][b_kq*4+1][b_col]=pk2(stB0.y);
        Bd[0][b_kq*4+2][b_col]=pk2(stB0.z); Bd[0][b_kq*4+3][b_col]=pk2(stB0.w);
        Bd[0][8+b_kq*4+0][b_col]=pk2(stB1.x); Bd[0][8+b_kq*4+1][b_col]=pk2(stB1.y);
        Bd[0][8+b_kq*4+2][b_col]=pk2(stB1.z); Bd[0][8+b_kq*4+3][b_col]=pk2(stB1.w);
    }

    int buf = 0;
    #pragma unroll 1
    for(int t=0;t<NKT;t++){
        __syncthreads();
        if(t+1 < NKT){
            const int gk = kbase + (t+1)*KT;
            if(tid < 128) stA = *(const float4*)(H + (size_t)a_row*Fc + gk + a_kq*4);
            const float* wrow = W + (size_t)(n0 + b_col)*Fc + gk;
            stB0 = *(const float4*)(wrow + b_kq*4);
            stB1 = *(const float4*)(wrow + 8 + b_kq*4);
        }
        // compute on current buffer
        #pragma unroll
        for(int k=0;k<KT;k++){
            ulonglong2 a01 = *(const ulonglong2*)&As[buf][k][rg*4];
            ulonglong2 b01 = *(const ulonglong2*)&Bd[buf][k][cg*4];
            ulonglong2 b23 = *(const ulonglong2*)&Bd[buf][k][cg*4+2];
            ffma2(acc[0][0], a01.x, b01.x); ffma2(acc[0][1], a01.x, b01.y);
            ffma2(acc[0][2], a01.x, b23.x); ffma2(acc[0][3], a01.x, b23.y);
            ffma2(acc[1][0], a01.y, b01.x); ffma2(acc[1][1], a01.y, b01.y);
            ffma2(acc[1][2], a01.y, b23.x); ffma2(acc[1][3], a01.y, b23.y);
        }
        if(t+1 < NKT){
            int nb = buf^1;
            if(tid < 128){
                As[nb][a_kq*4+0][a_row]=stA.x; As[nb][a_kq*4+1][a_row]=stA.y;
                As[nb][a_kq*4+2][a_row]=stA.z; As[nb][a_kq*4+3][a_row]=stA.w;
            }
            Bd[nb][b_kq*4+0][b_col]=pk2(stB0.x); Bd[nb][b_kq*4+1][b_col]=pk2(stB0.y);
            Bd[nb][b_kq*4+2][b_col]=pk2(stB0.z); Bd[nb][b_kq*4+3][b_col]=pk2(stB0.w);
            Bd[nb][8+b_kq*4+0][b_col]=pk2(stB1.x); Bd[nb][8+b_kq*4+1][b_col]=pk2(stB1.y);
            Bd[nb][8+b_kq*4+2][b_col]=pk2(stB1.z); Bd[nb][8+b_kq*4+3][b_col]=pk2(stB1.w);
        }
        buf ^= 1;
    }

    // epilogue: acc[p][c] holds rows (rg*4 + 2p, rg*4 + 2p + 1) for col n0+cg*4+c
    float* Pb = P + (size_t)blockIdx.y*Tc*G3;
    #pragma unroll
    for(int p=0;p<2;p++){
        float2 v0 = up2(acc[p][0]);
        float2 v1 = up2(acc[p][1]);
        float2 v2 = up2(acc[p][2]);
        float2 v3 = up2(acc[p][3]);
        int row = rg*4 + p*2;
        int col = n0 + cg*4;
        float4 e = {v0.x, v1.x, v2.x, v3.x};
        float4 o = {v0.y, v1.y, v2.y, v3.y};
        *(float4*)(Pb + (size_t)row*G3 + col)     = e;
        *(float4*)(Pb + (size_t)(row+1)*G3 + col) = o;
    }
}

// ---- GRU gate fuse: combine K-split partials + input gates + biases (float4) ----
__global__ void __launch_bounds__(256) k_gate(int b,
                                              const float* __restrict__ P,
                                              const float* __restrict__ Gi,
                                              const float* __restrict__ bhh,
                                              const float* __restrict__ Hprev,
                                              float* __restrict__ Hall)
{
    int i4 = blockIdx.x*256 + threadIdx.x;   // 16384 quads = 32*2048/4
    int row = i4 >> 9, j = (i4 & 511)*4;
    float4 gr = {0,0,0,0}, gz = {0,0,0,0}, gn = {0,0,0,0};
    #pragma unroll
    for(int ks=0;ks<KSPLIT;ks++){
        const float* p = P + ((size_t)ks*Tc + row)*G3;
        float4 a = *(const float4*)(p + j);
        float4 bv = *(const float4*)(p + 2048 + j);
        float4 c = *(const float4*)(p + 4096 + j);
        gr.x+=a.x; gr.y+=a.y; gr.z+=a.z; gr.w+=a.w;
        gz.x+=bv.x; gz.y+=bv.y; gz.z+=bv.z; gz.w+=bv.w;
        gn.x+=c.x; gn.y+=c.y; gn.z+=c.z; gn.w+=c.w;
    }
    const float* gi = Gi + ((size_t)b*Tc + row)*G3;
    float4 gir = *(const float4*)(gi + j);
    float4 giz = *(const float4*)(gi + 2048 + j);
    float4 gin = *(const float4*)(gi + 4096 + j);
    float4 br = *(const float4*)(bhh + j);
    float4 bz = *(const float4*)(bhh + 2048 + j);
    float4 bn = *(const float4*)(bhh + 4096 + j);
    float4 hp = *(const float4*)(Hprev + (size_t)row*Fc + j);
    float4 ho;
    {
        float r = 1.f/(1.f + expf(-(gir.x + gr.x + br.x)));
        float z = 1.f/(1.f + expf(-(giz.x + gz.x + bz.x)));
        float n = tanhf(gin.x + r*(gn.x + bn.x));
        ho.x = (1.f - z)*n + z*hp.x;
        r = 1.f/(1.f + expf(-(gir.y + gr.y + br.y)));
        z = 1.f/(1.f + expf(-(giz.y + gz.y + bz.y)));
        n = tanhf(gin.y + r*(gn.y + bn.y));
        ho.y = (1.f - z)*n + z*hp.y;
        r = 1.f/(1.f + expf(-(gir.z + gr.z + br.z)));
        z = 1.f/(1.f + expf(-(giz.z + gz.z + bz.z)));
        n = tanhf(gin.z + r*(gn.z + bn.z));
        ho.z = (1.f - z)*n + z*hp.z;
        r = 1.f/(1.f + expf(-(gir.w + gr.w + br.w)));
        z = 1.f/(1.f + expf(-(giz.w + gz.w + bz.w)));
        n = tanhf(gin.w + r*(gn.w + bn.w));
        ho.w = (1.f - z)*n + z*hp.w;
    }
    *(float4*)(Hall + ((size_t)b*Tc + row)*Fc + j) = ho;
}

// ---- temporal attention over T=32 per (b,f) ----
__global__ void __launch_bounds__(256) k_attn(const float* __restrict__ Emb,
                                              const float* __restrict__ Aw,
                                              const float* __restrict__ Ab,
                                              float* __restrict__ XN)
{
    __shared__ float sW[32][33];
    __shared__ float sB[32];
    int tid = threadIdx.x;
    for(int i=tid;i<1024;i+=256) sW[i>>5][i&31] = Aw[i];
    if(tid<32) sB[tid]=Ab[tid];
    __syncthreads();
    int g = blockIdx.x*256 + tid;        // b*2048 + f
    int b = g >> 11, f = g & 2047;
    float tA[32];
    #pragma unroll
    for(int t=0;t<32;t++) tA[t] = tanhf(Emb[((size_t)b*32 + t)*Fc + f]);
    float mx = -1e30f, aw[32];
    #pragma unroll
    for(int t2=0;t2<32;t2++){
        float s = sB[t2];
        #pragma unroll
        for(int t=0;t<32;t++) s += tA[t]*sW[t2][t];
        aw[t2]=s; mx = fmaxf(mx, s);
    }
    float den=0.f, num=0.f;
    #pragma unroll
    for(int t=0;t<32;t++){ float e = expf(aw[t]-mx); den += e; num += e*tA[t]; }
    XN[g] = tanhf(num/den);
}

// ---- GAT projections: XL = X@Wl^T+bl, XR = X@Wr^T+br (64x64) ----
__global__ void __launch_bounds__(256) k_lin64(const float* __restrict__ X,
                                               const float* __restrict__ Wl, const float* __restrict__ bl,
                                               const float* __restrict__ Wr, const float* __restrict__ br,
                                               float* __restrict__ XL, float* __restrict__ XR)
{
    __shared__ float sX[64][65];
    __shared__ float sW[64][65];
    int tid = threadIdx.x;
    int r0 = blockIdx.x*64;
    for(int i=tid;i<4096;i+=256){ int r=i>>6, c=i&63; sX[r][c]=X[(size_t)(r0+r)*64+c]; }
    for(int i=tid;i<4096;i+=256){ int r=i>>6, c=i&63; sW[r][c]=Wl[i]; }
    __syncthreads();
    int r = tid & 63, cq = tid >> 6;
    #pragma unroll 4
    for(int cc=0; cc<16; cc++){
        int c = cq*16 + cc;
        float s = bl[c];
        #pragma unroll
        for(int k=0;k<64;k++) s += sX[r][k]*sW[c][k];
        XL[(size_t)(r0+r)*64 + c] = s;
    }
    __syncthreads();
    for(int i=tid;i<4096;i+=256){ int rr=i>>6, c=i&63; sW[rr][c]=Wr[i]; }
    __syncthreads();
    #pragma unroll 4
    for(int cc=0; cc<16; cc++){
        int c = cq*16 + cc;
        float s = br[c];
        #pragma unroll
        for(int k=0;k<64;k++) s += sX[r][k]*sW[c][k];
        XR[(size_t)(r0+r)*64 + c] = s;
    }
}

// ---- GATv2 on dense 32x32 block graph; one warp per dst node; tanh output ----
__global__ void __launch_bounds__(128) k_gat(const float* __restrict__ XL,
                                             const float* __restrict__ XR,
                                             const float* __restrict__ att,
                                             const float* __restrict__ bias,
                                             float* __restrict__ OUT)
{
    int w = threadIdx.x >> 5, lane = threadIdx.x & 31;
    int g = blockIdx.x >> 3;
    int d = ((blockIdx.x & 7) << 2) + w;
    int nd = g*32 + d;
    float xr0 = XR[(size_t)nd*64 + lane];
    float xr1 = XR[(size_t)nd*64 + 32 + lane];
    float a0 = att[lane], a1 = att[lane+32];
    const float* xlg = XL + (size_t)g*32*64;
    float lg[32];
    #pragma unroll
    for(int s=0;s<32;s++){
        float u = xlg[s*64 + lane]      + xr0;
        float v = xlg[s*64 + 32 + lane] + xr1;
        u = u>0.f ? u : 0.2f*u;
        v = v>0.f ? v : 0.2f*v;
        float t = u*a0 + v*a1;
        #pragma unroll
        for(int o=16;o>0;o>>=1) t += __shfl_xor_sync(0xffffffffu, t, o);
        lg[s] = t;
    }
    float m = -1e30f;
    #pragma unroll
    for(int s=0;s<32;s++) m = fmaxf(m, lg[s]);
    float den = 0.f;
    #pragma unroll
    for(int s=0;s<32;s++){ lg[s] = expf(lg[s]-m); den += lg[s]; }
    float inv = 1.f/den, o0=0.f, o1=0.f;
    #pragma unroll
    for(int s=0;s<32;s++){
        float al = lg[s]*inv;
        o0 += al * xlg[s*64 + lane];
        o1 += al * xlg[s*64 + 32 + lane];
    }
    OUT[(size_t)nd*64 + lane]      = tanhf(o0 + bias[lane]);
    OUT[(size_t)nd*64 + 32 + lane] = tanhf(o1 + bias[lane+32]);
}

// ---- fusion concat ----
__global__ void k_fus(const float* __restrict__ XN, const float* __restrict__ G0,
                      const float* __restrict__ G1, float* __restrict__ FUS)
{
    int i = blockIdx.x*256 + threadIdx.x;  // 4096*128
    int n = i >> 7, q = i & 127;
    FUS[i] = (q < 64) ? XN[(size_t)n*64 + q]
                      : (G0[(size_t)n*64 + q-64] + G1[(size_t)n*64 + q-64]);
}

// ---- capsule routing (3 iters) + final head ----
__global__ void __launch_bounds__(64) k_route(const float* __restrict__ PR,
                                              const float* __restrict__ Fw,
                                              const float* __restrict__ Fb,
                                              float* __restrict__ out)
{
    int n = blockIdx.x, l = threadIdx.x;
    const float* base = PR + (size_t)n*65536 + l;   // idx: c*2048 + o*64
    float o0[32], o1[32], pc[32], te[32];
    #pragma unroll
    for(int o=0;o<32;o++) o0[o]=0.f;
    for(int c=0;c<32;c++){
        const float* pcol = base + (size_t)c*2048;
        #pragma unroll
        for(int o=0;o<32;o++) o0[o] += pcol[o*64];
    }
    #pragma unroll
    for(int o=0;o<32;o++){ o0[o] *= (1.f/32.f); o1[o]=0.f; }
    for(int c=0;c<32;c++){
        const float* pcol = base + (size_t)c*2048;
        float m = -1e30f;
        #pragma unroll
        for(int o=0;o<32;o++){ pc[o]=pcol[o*64]; float lgv = pc[o]*o0[o]; te[o]=lgv; m = fmaxf(m,lgv); }
        float den=0.f;
        #pragma unroll
        for(int o=0;o<32;o++){ te[o]=expf(te[o]-m); den+=te[o]; }
        float inv = 1.f/den;
        #pragma unroll
        for(int o=0;o<32;o++) o1[o] += te[o]*inv*pc[o];
    }
    #pragma unroll
    for(int o=0;o<32;o++){ o0[o] += o1[o]; o1[o]=0.f; }
    for(int c=0;c<32;c++){
        const float* pcol = base + (size_t)c*2048;
        float m = -1e30f;
        #pragma unroll
        for(int o=0;o<32;o++){ pc[o]=pcol[o*64]; float lgv = pc[o]*o0[o]; te[o]=lgv; m = fmaxf(m,lgv); }
        float den=0.f;
        #pragma unroll
        for(int o=0;o<32;o++){ te[o]=expf(te[o]-m); den+=te[o]; }
        float inv = 1.f/den;
        #pragma unroll
        for(int o=0;o<32;o++) o1[o] += te[o]*inv*pc[o];
    }
    __shared__ float sc[32][65];
    #pragma unroll
    for(int o=0;o<32;o++) sc[o][l] = tanhf(o1[o]);
    __syncthreads();
    for(int q=0;q<16;q++){
        int idx = l*16 + q;
        int o = idx >> 5, d2 = idx & 31;
        float s = Fb[d2];
        #pragma unroll
        for(int ll=0;ll<64;ll++) s += sc[o][ll]*Fw[d2*64+ll];
        out[(size_t)n*1024 + o*32 + d2] = tanhf(s);
    }
}

extern "C" void kernel_launch(void* const* d_in, const int* in_sizes, int n_in,
                              void* d_out, int out_size)
{
    const float* inputs = (const float*)d_in[0];
    const float* Wih0 = (const float*)d_in[1];
    const float* Whh0 = (const float*)d_in[2];
    const float* bih0 = (const float*)d_in[3];
    const float* bhh0 = (const float*)d_in[4];
    const float* Wih1 = (const float*)d_in[5];
    const float* Whh1 = (const float*)d_in[6];
    const float* bih1 = (const float*)d_in[7];
    const float* bhh1 = (const float*)d_in[8];
    const float* A_w  = (const float*)d_in[9];
    const float* A_b  = (const float*)d_in[10];
    const float* g0_Wl = (const float*)d_in[11];
    const float* g0_bl = (const float*)d_in[12];
    const float* g0_Wr = (const float*)d_in[13];
    const float* g0_br = (const float*)d_in[14];
    const float* g0_att = (const float*)d_in[15];
    const float* g0_bias = (const float*)d_in[16];
    const float* g1_Wl = (const float*)d_in[17];
    const float* g1_bl = (const float*)d_in[18];
    const float* g1_Wr = (const float*)d_in[19];
    const float* g1_br = (const float*)d_in[20];
    const float* g1_att = (const float*)d_in[21];
    const float* g1_bias = (const float*)d_in[22];
    const float* W_caps = (const float*)d_in[23];
    const float* F_w = (const float*)d_in[24];
    const float* F_b = (const float*)d_in[25];
    float* out = (float*)d_out;

    float *Xs,*Gi,*H0,*Emb,*hz,*P,*XN,*XL,*XR,*G0,*G1,*FUS,*PR;
    cudaGetSymbolAddress((void**)&Xs,  g_Xs);
    cudaGetSymbolAddress((void**)&Gi,  g_Gi);
    cudaGetSymbolAddress((void**)&H0,  g_H0);
    cudaGetSymbolAddress((void**)&Emb, g_Emb);
    cudaGetSymbolAddress((void**)&hz,  g_hz);
    cudaGetSymbolAddress((void**)&P,   g_P);
    cudaGetSymbolAddress((void**)&XN,  g_XN);
    cudaGetSymbolAddress((void**)&XL,  g_XL);
    cudaGetSymbolAddress((void**)&XR,  g_XR);
    cudaGetSymbolAddress((void**)&G0,  g_G0);
    cudaGetSymbolAddress((void**)&G1,  g_G1);
    cudaGetSymbolAddress((void**)&FUS, g_FUS);
    cudaGetSymbolAddress((void**)&PR,  g_PR);

    const int NTOT = Bc*Tc*Fc;
    k_zero<<<(Tc*Fc+255)/256, 256>>>(hz, Tc*Fc);
    k_sanitize<<<(NTOT+255)/256, 256>>>(inputs, Xs, NTOT);

    // layer 0
    k_sgemm<<<dim3(G3/128, (Bc*Tc)/128), 256>>>(Xs, Wih0, bih0, Gi, G3, Fc);
    for(int b=0;b<Bc;b++){
        const float* hp = b ? (H0 + (size_t)(b-1)*Tc*Fc) : hz;
        k_rgemm<<<dim3(G3/NTILE, KSPLIT), 256>>>(hp, Whh0, P);
        k_gate<<<64, 256>>>(b, P, Gi, bhh0, hp, H0);
    }
    // layer 1
    k_sgemm<<<dim3(G3/128, (Bc*Tc)/128), 256>>>(H0, Wih1, bih1, Gi, G3, Fc);
    for(int b=0;b<Bc;b++){
        const float* hp = b ? (Emb + (size_t)(b-1)*Tc*Fc) : hz;
        k_rgemm<<<dim3(G3/NTILE, KSPLIT), 256>>>(hp, Whh1, P);
        k_gate<<<64, 256>>>(b, P, Gi, bhh1, hp, Emb);
    }
    // attention -> node features
    k_attn<<<(Bc*Fc)/256, 256>>>(Emb, A_w, A_b, XN);
    // GAT layer 0
    k_lin64<<<Nn/64, 256>>>(XN, g0_Wl, g0_bl, g0_Wr, g0_br, XL, XR);
    k_gat<<<1024, 128>>>(XL, XR, g0_att, g0_bias, G0);
    // GAT layer 1
    k_lin64<<<Nn/64, 256>>>(G0, g1_Wl, g1_bl, g1_Wr, g1_br, XL, XR);
    k_gat<<<1024, 128>>>(XL, XR, g1_att, g1_bias, G1);
    // fusion + capsule priors
    k_fus<<<(Nn*128)/256, 256>>>(XN, G0, G1, FUS);
    k_sgemm<<<dim3(2048/128, Nn/128), 256>>>(FUS, W_caps, nullptr, PR, 2048, 128);
    // routing + head
    k_route<<<Bc, 64>>>(PR, F_w, F_b, out);
}

// round 6
// speedup vs baseline: 1.4462x; 1.4462x over previous
#include <cuda_runtime.h>
#include <cuda_bf16.h>
#include <math.h>
#include <stdint.h>

#define Bc 128
#define Tc 32
#define Fc 2048
#define G3 6144
#define Hc 64
#define Nn 4096
#define KSPLIT 32
#define KCHUNK 64    // Fc / KSPLIT
#define KT 16
#define NKT (KCHUNK/KT)
#define NTILE 256

// ---- static scratch (no cudaMalloc allowed) ----
__device__ float g_Xs[Bc*Tc*Fc];
__device__ float g_Gi[(size_t)Bc*Tc*G3];
__device__ float g_H0[Bc*Tc*Fc];
__device__ float g_Emb[Bc*Tc*Fc];
__device__ float g_hz[Tc*Fc];
__device__ float g_P[(size_t)KSPLIT*Tc*G3];
__device__ float g_XN[Nn*Hc];
__device__ float g_XL[Nn*Hc];
__device__ float g_XR[Nn*Hc];
__device__ float g_G0[Nn*Hc];
__device__ float g_G1[Nn*Hc];
__device__ float g_FUS[Nn*2*Hc];
__device__ float g_PR[(size_t)Nn*2048];

// ---- packed f32x2 helpers ----
__device__ __forceinline__ unsigned long long pk2(float x){
    unsigned long long r; asm("mov.b64 %0,{%1,%1};" : "=l"(r) : "f"(x)); return r;
}
__device__ __forceinline__ void ffma2(unsigned long long& d, unsigned long long a, unsigned long long b){
    asm("fma.rn.f32x2 %0,%1,%2,%0;" : "+l"(d) : "l"(a), "l"(b));
}
__device__ __forceinline__ float2 up2(unsigned long long v){
    float2 r; asm("mov.b64 {%0,%1},%2;" : "=f"(r.x), "=f"(r.y) : "l"(v)); return r;
}

// ---- utility ----
__global__ void k_zero(float* p, int n){ int i=blockIdx.x*256+threadIdx.x; if(i<n) p[i]=0.f; }

__global__ void k_sanitize(const float* __restrict__ in, float* __restrict__ out, int n){
    int i = blockIdx.x*256 + threadIdx.x;
    if(i<n){
        float v = in[i];
        if (isnan(v)) v = 0.f;
        else if (isinf(v)) v = (v>0.f) ? 1.0f : -3.4028234663852886e38f;
        out[i] = v;
    }
}

// ---- big SGEMM: C[M,N] = A[M,K] @ B[N,K]^T (+bias), 128x128 tile, f32x2 ----
__global__ void __launch_bounds__(256) k_sgemm(const float* __restrict__ A,
                                               const float* __restrict__ Bm,
                                               const float* __restrict__ bias,
                                               float* __restrict__ C,
                                               int Ncols, int K)
{
    __shared__ float As[8][128];
    __shared__ float Bs[8][128];
    const int tid = threadIdx.x;
    const int tx = tid & 15, ty = tid >> 4;
    const int m0 = blockIdx.y*128, n0 = blockIdx.x*128;
    const int lr = tid >> 1, lc = (tid & 1)*4;
    const float* Ap = A + (size_t)(m0+lr)*K + lc;
    const float* Bp = Bm + (size_t)(n0+lr)*K + lc;

    unsigned long long acc[8][4];
    #pragma unroll
    for(int i=0;i<8;i++)
        #pragma unroll
        for(int j=0;j<4;j++) acc[i][j]=0ULL;

    for(int k0=0;k0<K;k0+=8){
        float4 av = *(const float4*)(Ap + k0);
        float4 bv = *(const float4*)(Bp + k0);
        __syncthreads();
        As[lc+0][lr]=av.x; As[lc+1][lr]=av.y; As[lc+2][lr]=av.z; As[lc+3][lr]=av.w;
        Bs[lc+0][lr]=bv.x; Bs[lc+1][lr]=bv.y; Bs[lc+2][lr]=bv.z; Bs[lc+3][lr]=bv.w;
        __syncthreads();
        #pragma unroll
        for(int k=0;k<8;k++){
            float4 a0 = *(const float4*)&As[k][ty*8];
            float4 a1 = *(const float4*)&As[k][ty*8+4];
            ulonglong2 b01 = *(const ulonglong2*)&Bs[k][tx*8];
            ulonglong2 b23 = *(const ulonglong2*)&Bs[k][tx*8+4];
            unsigned long long aa[8];
            aa[0]=pk2(a0.x); aa[1]=pk2(a0.y); aa[2]=pk2(a0.z); aa[3]=pk2(a0.w);
            aa[4]=pk2(a1.x); aa[5]=pk2(a1.y); aa[6]=pk2(a1.z); aa[7]=pk2(a1.w);
            #pragma unroll
            for(int i=0;i<8;i++){
                ffma2(acc[i][0], aa[i], b01.x);
                ffma2(acc[i][1], aa[i], b01.y);
                ffma2(acc[i][2], aa[i], b23.x);
                ffma2(acc[i][3], aa[i], b23.y);
            }
        }
    }
    #pragma unroll
    for(int i=0;i<8;i++){
        int row = m0 + ty*8 + i;
        #pragma unroll
        for(int j=0;j<4;j++){
            float2 v = up2(acc[i][j]);
            int col = n0 + tx*8 + j*2;
            float b0 = bias ? bias[col]   : 0.f;
            float b1 = bias ? bias[col+1] : 0.f;
            C[(size_t)row*Ncols + col]   = v.x + b0;
            C[(size_t)row*Ncols + col+1] = v.y + b1;
        }
    }
}

// ---- recurrent GEMM: P[ks][32][6144] partials of H[32,2048] @ W[6144,2048]^T ----
// R4 tiling (known good): tile M=32 x N=256, KT=16 double-buffered,
// thread tile 8 rows (4 f32x2 pairs) x 4 cols, A read as packed pairs (no movs).
// KCHUNK=64 -> grid (24, 32) = 768 CTAs; launch_bounds(256,4) for 4 CTAs/SM.
__global__ void __launch_bounds__(256, 4) k_rgemm(const float* __restrict__ H,
                                                  const float* __restrict__ W,
                                                  float* __restrict__ P)
{
    __shared__ float As[2][KT][36];
    __shared__ float Bs[2][KT][260];
    const int tid = threadIdx.x;
    const int cg = tid & 63;        // 64 col groups x 4 cols
    const int rg = tid >> 6;        // 4 row groups x 8 rows
    const int n0 = blockIdx.x * NTILE;
    const int kbase = blockIdx.y * KCHUNK;

    const int lr = tid >> 2;        // 0..63
    const int lq = tid & 3;         // k-quad

    unsigned long long acc[4][4];
    #pragma unroll
    for(int i=0;i<4;i++)
        #pragma unroll
        for(int j=0;j<4;j++) acc[i][j]=0ULL;

    float4 stA; float4 stB[4];

    // prologue: load ktile 0
    {
        const int gk = kbase;
        if(tid < 128) stA = *(const float4*)(H + (size_t)lr*Fc + gk + lq*4);
        #pragma unroll
        for(int p=0;p<4;p++)
            stB[p] = *(const float4*)(W + (size_t)(n0 + p*64 + lr)*Fc + gk + lq*4);
        if(tid < 128){
            As[0][lq*4+0][lr]=stA.x; As[0][lq*4+1][lr]=stA.y;
            As[0][lq*4+2][lr]=stA.z; As[0][lq*4+3][lr]=stA.w;
        }
        #pragma unroll
        for(int p=0;p<4;p++){
            int col = p*64 + lr;
            Bs[0][lq*4+0][col]=stB[p].x; Bs[0][lq*4+1][col]=stB[p].y;
            Bs[0][lq*4+2][col]=stB[p].z; Bs[0][lq*4+3][col]=stB[p].w;
        }
    }

    int buf = 0;
    #pragma unroll 1
    for(int t=0;t<NKT;t++){
        __syncthreads();
        if(t+1 < NKT){
            const int gk = kbase + (t+1)*KT;
            if(tid < 128) stA = *(const float4*)(H + (size_t)lr*Fc + gk + lq*4);
            #pragma unroll
            for(int p=0;p<4;p++)
                stB[p] = *(const float4*)(W + (size_t)(n0 + p*64 + lr)*Fc + gk + lq*4);
        }
        // compute current buffer
        #pragma unroll
        for(int k=0;k<KT;k++){
            ulonglong2 a01 = *(const ulonglong2*)&As[buf][k][rg*8];
            ulonglong2 a23 = *(const ulonglong2*)&As[buf][k][rg*8+4];
            float4 bf = *(const float4*)&Bs[buf][k][cg*4];
            unsigned long long b0=pk2(bf.x), b1=pk2(bf.y), b2=pk2(bf.z), b3=pk2(bf.w);
            ffma2(acc[0][0], a01.x, b0); ffma2(acc[0][1], a01.x, b1);
            ffma2(acc[0][2], a01.x, b2); ffma2(acc[0][3], a01.x, b3);
            ffma2(acc[1][0], a01.y, b0); ffma2(acc[1][1], a01.y, b1);
            ffma2(acc[1][2], a01.y, b2); ffma2(acc[1][3], a01.y, b3);
            ffma2(acc[2][0], a23.x, b0); ffma2(acc[2][1], a23.x, b1);
            ffma2(acc[2][2], a23.x, b2); ffma2(acc[2][3], a23.x, b3);
            ffma2(acc[3][0], a23.y, b0); ffma2(acc[3][1], a23.y, b1);
            ffma2(acc[3][2], a23.y, b2); ffma2(acc[3][3], a23.y, b3);
        }
        if(t+1 < NKT){
            int nb = buf^1;
            if(tid < 128){
                As[nb][lq*4+0][lr]=stA.x; As[nb][lq*4+1][lr]=stA.y;
                As[nb][lq*4+2][lr]=stA.z; As[nb][lq*4+3][lr]=stA.w;
            }
            #pragma unroll
            for(int p=0;p<4;p++){
                int col = p*64 + lr;
                Bs[nb][lq*4+0][col]=stB[p].x; Bs[nb][lq*4+1][col]=stB[p].y;
                Bs[nb][lq*4+2][col]=stB[p].z; Bs[nb][lq*4+3][col]=stB[p].w;
            }
        }
        buf ^= 1;
    }

    float* Pb = P + (size_t)blockIdx.y*Tc*G3;
    #pragma unroll
    for(int rp=0;rp<4;rp++){
        int row = rg*8 + rp*2;
        #pragma unroll
        for(int c=0;c<4;c++){
            float2 v = up2(acc[rp][c]);
            int col = n0 + cg*4 + c;
            Pb[(size_t)row*G3 + col]     = v.x;
            Pb[(size_t)(row+1)*G3 + col] = v.y;
        }
    }
}

// ---- GRU gate fuse: combine K-split partials + input gates + biases (float4) ----
__global__ void __launch_bounds__(256) k_gate(int b,
                                              const float* __restrict__ P,
                                              const float* __restrict__ Gi,
                                              const float* __restrict__ bhh,
                                              const float* __restrict__ Hprev,
                                              float* __restrict__ Hall)
{
    int i4 = blockIdx.x*256 + threadIdx.x;   // 16384 quads = 32*2048/4
    int row = i4 >> 9, j = (i4 & 511)*4;
    float4 gr = {0,0,0,0}, gz = {0,0,0,0}, gn = {0,0,0,0};
    #pragma unroll 8
    for(int ks=0;ks<KSPLIT;ks++){
        const float* p = P + ((size_t)ks*Tc + row)*G3;
        float4 a = *(const float4*)(p + j);
        float4 bv = *(const float4*)(p + 2048 + j);
        float4 c = *(const float4*)(p + 4096 + j);
        gr.x+=a.x; gr.y+=a.y; gr.z+=a.z; gr.w+=a.w;
        gz.x+=bv.x; gz.y+=bv.y; gz.z+=bv.z; gz.w+=bv.w;
        gn.x+=c.x; gn.y+=c.y; gn.z+=c.z; gn.w+=c.w;
    }
    const float* gi = Gi + ((size_t)b*Tc + row)*G3;
    float4 gir = *(const float4*)(gi + j);
    float4 giz = *(const float4*)(gi + 2048 + j);
    float4 gin = *(const float4*)(gi + 4096 + j);
    float4 br = *(const float4*)(bhh + j);
    float4 bz = *(const float4*)(bhh + 2048 + j);
    float4 bn = *(const float4*)(bhh + 4096 + j);
    float4 hp = *(const float4*)(Hprev + (size_t)row*Fc + j);
    float4 ho;
    {
        float r = 1.f/(1.f + expf(-(gir.x + gr.x + br.x)));
        float z = 1.f/(1.f + expf(-(giz.x + gz.x + bz.x)));
        float n = tanhf(gin.x + r*(gn.x + bn.x));
        ho.x = (1.f - z)*n + z*hp.x;
        r = 1.f/(1.f + expf(-(gir.y + gr.y + br.y)));
        z = 1.f/(1.f + expf(-(giz.y + gz.y + bz.y)));
        n = tanhf(gin.y + r*(gn.y + bn.y));
        ho.y = (1.f - z)*n + z*hp.y;
        r = 1.f/(1.f + expf(-(gir.z + gr.z + br.z)));
        z = 1.f/(1.f + expf(-(giz.z + gz.z + bz.z)));
        n = tanhf(gin.z + r*(gn.z + bn.z));
        ho.z = (1.f - z)*n + z*hp.z;
        r = 1.f/(1.f + expf(-(gir.w + gr.w + br.w)));
        z = 1.f/(1.f + expf(-(giz.w + gz.w + bz.w)));
        n = tanhf(gin.w + r*(gn.w + bn.w));
        ho.w = (1.f - z)*n + z*hp.w;
    }
    *(float4*)(Hall + ((size_t)b*Tc + row)*Fc + j) = ho;
}

// ---- temporal attention over T=32 per (b,f) ----
__global__ void __launch_bounds__(256) k_attn(const float* __restrict__ Emb,
                                              const float* __restrict__ Aw,
                                              const float* __restrict__ Ab,
                                              float* __restrict__ XN)
{
    __shared__ float sW[32][33];
    __shared__ float sB[32];
    int tid = threadIdx.x;
    for(int i=tid;i<1024;i+=256) sW[i>>5][i&31] = Aw[i];
    if(tid<32) sB[tid]=Ab[tid];
    __syncthreads();
    int g = blockIdx.x*256 + tid;        // b*2048 + f
    int b = g >> 11, f = g & 2047;
    float tA[32];
    #pragma unroll
    for(int t=0;t<32;t++) tA[t] = tanhf(Emb[((size_t)b*32 + t)*Fc + f]);
    float mx = -1e30f, aw[32];
    #pragma unroll
    for(int t2=0;t2<32;t2++){
        float s = sB[t2];
        #pragma unroll
        for(int t=0;t<32;t++) s += tA[t]*sW[t2][t];
        aw[t2]=s; mx = fmaxf(mx, s);
    }
    float den=0.f, num=0.f;
    #pragma unroll
    for(int t=0;t<32;t++){ float e = expf(aw[t]-mx); den += e; num += e*tA[t]; }
    XN[g] = tanhf(num/den);
}

// ---- GAT projections: XL = X@Wl^T+bl, XR = X@Wr^T+br (64x64) ----
__global__ void __launch_bounds__(256) k_lin64(const float* __restrict__ X,
                                               const float* __restrict__ Wl, const float* __restrict__ bl,
                                               const float* __restrict__ Wr, const float* __restrict__ br,
                                               float* __restrict__ XL, float* __restrict__ XR)
{
    __shared__ float sX[64][65];
    __shared__ float sW[64][65];
    int tid = threadIdx.x;
    int r0 = blockIdx.x*64;
    for(int i=tid;i<4096;i+=256){ int r=i>>6, c=i&63; sX[r][c]=X[(size_t)(r0+r)*64+c]; }
    for(int i=tid;i<4096;i+=256){ int r=i>>6, c=i&63; sW[r][c]=Wl[i]; }
    __syncthreads();
    int r = tid & 63, cq = tid >> 6;
    #pragma unroll 4
    for(int cc=0; cc<16; cc++){
        int c = cq*16 + cc;
        float s = bl[c];
        #pragma unroll
        for(int k=0;k<64;k++) s += sX[r][k]*sW[c][k];
        XL[(size_t)(r0+r)*64 + c] = s;
    }
    __syncthreads();
    for(int i=tid;i<4096;i+=256){ int rr=i>>6, c=i&63; sW[rr][c]=Wr[i]; }
    __syncthreads();
    #pragma unroll 4
    for(int cc=0; cc<16; cc++){
        int c = cq*16 + cc;
        float s = br[c];
        #pragma unroll
        for(int k=0;k<64;k++) s += sX[r][k]*sW[c][k];
        XR[(size_t)(r0+r)*64 + c] = s;
    }
}

// ---- GATv2 on dense 32x32 block graph; one warp per dst node; tanh output ----
__global__ void __launch_bounds__(128) k_gat(const float* __restrict__ XL,
                                             const float* __restrict__ XR,
                                             const float* __restrict__ att,
                                             const float* __restrict__ bias,
                                             float* __restrict__ OUT)
{
    int w = threadIdx.x >> 5, lane = threadIdx.x & 31;
    int g = blockIdx.x >> 3;
    int d = ((blockIdx.x & 7) << 2) + w;
    int nd = g*32 + d;
    float xr0 = XR[(size_t)nd*64 + lane];
    float xr1 = XR[(size_t)nd*64 + 32 + lane];
    float a0 = att[lane], a1 = att[lane+32];
    const float* xlg = XL + (size_t)g*32*64;
    float lg[32];
    #pragma unroll
    for(int s=0;s<32;s++){
        float u = xlg[s*64 + lane]      + xr0;
        float v = xlg[s*64 + 32 + lane] + xr1;
        u = u>0.f ? u : 0.2f*u;
        v = v>0.f ? v : 0.2f*v;
        float t = u*a0 + v*a1;
        #pragma unroll
        for(int o=16;o>0;o>>=1) t += __shfl_xor_sync(0xffffffffu, t, o);
        lg[s] = t;
    }
    float m = -1e30f;
    #pragma unroll
    for(int s=0;s<32;s++) m = fmaxf(m, lg[s]);
    float den = 0.f;
    #pragma unroll
    for(int s=0;s<32;s++){ lg[s] = expf(lg[s]-m); den += lg[s]; }
    float inv = 1.f/den, o0=0.f, o1=0.f;
    #pragma unroll
    for(int s=0;s<32;s++){
        float al = lg[s]*inv;
        o0 += al * xlg[s*64 + lane];
        o1 += al * xlg[s*64 + 32 + lane];
    }
    OUT[(size_t)nd*64 + lane]      = tanhf(o0 + bias[lane]);
    OUT[(size_t)nd*64 + 32 + lane] = tanhf(o1 + bias[lane+32]);
}

// ---- fusion concat ----
__global__ void k_fus(const float* __restrict__ XN, const float* __restrict__ G0,
                      const float* __restrict__ G1, float* __restrict__ FUS)
{
    int i = blockIdx.x*256 + threadIdx.x;  // 4096*128
    int n = i >> 7, q = i & 127;
    FUS[i] = (q < 64) ? XN[(size_t)n*64 + q]
                      : (G0[(size_t)n*64 + q-64] + G1[(size_t)n*64 + q-64]);
}

// ---- capsule routing (3 iters) + final head ----
__global__ void __launch_bounds__(64) k_route(const float* __restrict__ PR,
                                              const float* __restrict__ Fw,
                                              const float* __restrict__ Fb,
                                              float* __restrict__ out)
{
    int n = blockIdx.x, l = threadIdx.x;
    const float* base = PR + (size_t)n*65536 + l;   // idx: c*2048 + o*64
    float o0[32], o1[32], pc[32], te[32];
    #pragma unroll
    for(int o=0;o<32;o++) o0[o]=0.f;
    for(int c=0;c<32;c++){
        const float* pcol = base + (size_t)c*2048;
        #pragma unroll
        for(int o=0;o<32;o++) o0[o] += pcol[o*64];
    }
    #pragma unroll
    for(int o=0;o<32;o++){ o0[o] *= (1.f/32.f); o1[o]=0.f; }
    for(int c=0;c<32;c++){
        const float* pcol = base + (size_t)c*2048;
        float m = -1e30f;
        #pragma unroll
        for(int o=0;o<32;o++){ pc[o]=pcol[o*64]; float lgv = pc[o]*o0[o]; te[o]=lgv; m = fmaxf(m,lgv); }
        float den=0.f;
        #pragma unroll
        for(int o=0;o<32;o++){ te[o]=expf(te[o]-m); den+=te[o]; }
        float inv = 1.f/den;
        #pragma unroll
        for(int o=0;o<32;o++) o1[o] += te[o]*inv*pc[o];
    }
    #pragma unroll
    for(int o=0;o<32;o++){ o0[o] += o1[o]; o1[o]=0.f; }
    for(int c=0;c<32;c++){
        const float* pcol = base + (size_t)c*2048;
        float m = -1e30f;
        #pragma unroll
        for(int o=0;o<32;o++){ pc[o]=pcol[o*64]; float lgv = pc[o]*o0[o]; te[o]=lgv; m = fmaxf(m,lgv); }
        float den=0.f;
        #pragma unroll
        for(int o=0;o<32;o++){ te[o]=expf(te[o]-m); den+=te[o]; }
        float inv = 1.f/den;
        #pragma unroll
        for(int o=0;o<32;o++) o1[o] += te[o]*inv*pc[o];
    }
    __shared__ float sc[32][65];
    #pragma unroll
    for(int o=0;o<32;o++) sc[o][l] = tanhf(o1[o]);
    __syncthreads();
    for(int q=0;q<16;q++){
        int idx = l*16 + q;
        int o = idx >> 5, d2 = idx & 31;
        float s = Fb[d2];
        #pragma unroll
        for(int ll=0;ll<64;ll++) s += sc[o][ll]*Fw[d2*64+ll];
        out[(size_t)n*1024 + o*32 + d2] = tanhf(s);
    }
}

extern "C" void kernel_launch(void* const* d_in, const int* in_sizes, int n_in,
                              void* d_out, int out_size)
{
    const float* inputs = (const float*)d_in[0];
    const float* Wih0 = (const float*)d_in[1];
    const float* Whh0 = (const float*)d_in[2];
    const float* bih0 = (const float*)d_in[3];
    const float* bhh0 = (const float*)d_in[4];
    const float* Wih1 = (const float*)d_in[5];
    const float* Whh1 = (const float*)d_in[6];
    const float* bih1 = (const float*)d_in[7];
    const float* bhh1 = (const float*)d_in[8];
    const float* A_w  = (const float*)d_in[9];
    const float* A_b  = (const float*)d_in[10];
    const float* g0_Wl = (const float*)d_in[11];
    const float* g0_bl = (const float*)d_in[12];
    const float* g0_Wr = (const float*)d_in[13];
    const float* g0_br = (const float*)d_in[14];
    const float* g0_att = (const float*)d_in[15];
    const float* g0_bias = (const float*)d_in[16];
    const float* g1_Wl = (const float*)d_in[17];
    const float* g1_bl = (const float*)d_in[18];
    const float* g1_Wr = (const float*)d_in[19];
    const float* g1_br = (const float*)d_in[20];
    const float* g1_att = (const float*)d_in[21];
    const float* g1_bias = (const float*)d_in[22];
    const float* W_caps = (const float*)d_in[23];
    const float* F_w = (const float*)d_in[24];
    const float* F_b = (const float*)d_in[25];
    float* out = (float*)d_out;

    float *Xs,*Gi,*H0,*Emb,*hz,*P,*XN,*XL,*XR,*G0,*G1,*FUS,*PR;
    cudaGetSymbolAddress((void**)&Xs,  g_Xs);
    cudaGetSymbolAddress((void**)&Gi,  g_Gi);
    cudaGetSymbolAddress((void**)&H0,  g_H0);
    cudaGetSymbolAddress((void**)&Emb, g_Emb);
    cudaGetSymbolAddress((void**)&hz,  g_hz);
    cudaGetSymbolAddress((void**)&P,   g_P);
    cudaGetSymbolAddress((void**)&XN,  g_XN);
    cudaGetSymbolAddress((void**)&XL,  g_XL);
    cudaGetSymbolAddress((void**)&XR,  g_XR);
    cudaGetSymbolAddress((void**)&G0,  g_G0);
    cudaGetSymbolAddress((void**)&G1,  g_G1);
    cudaGetSymbolAddress((void**)&FUS, g_FUS);
    cudaGetSymbolAddress((void**)&PR,  g_PR);

    const int NTOT = Bc*Tc*Fc;
    k_zero<<<(Tc*Fc+255)/256, 256>>>(hz, Tc*Fc);
    k_sanitize<<<(NTOT+255)/256, 256>>>(inputs, Xs, NTOT);

    // layer 0
    k_sgemm<<<dim3(G3/128, (Bc*Tc)/128), 256>>>(Xs, Wih0, bih0, Gi, G3, Fc);
    for(int b=0;b<Bc;b++){
        const float* hp = b ? (H0 + (size_t)(b-1)*Tc*Fc) : hz;
        k_rgemm<<<dim3(G3/NTILE, KSPLIT), 256>>>(hp, Whh0, P);
        k_gate<<<64, 256>>>(b, P, Gi, bhh0, hp, H0);
    }
    // layer 1
    k_sgemm<<<dim3(G3/128, (Bc*Tc)/128), 256>>>(H0, Wih1, bih1, Gi, G3, Fc);
    for(int b=0;b<Bc;b++){
        const float* hp = b ? (Emb + (size_t)(b-1)*Tc*Fc) : hz;
        k_rgemm<<<dim3(G3/NTILE, KSPLIT), 256>>>(hp, Whh1, P);
        k_gate<<<64, 256>>>(b, P, Gi, bhh1, hp, Emb);
    }
    // attention -> node features
    k_attn<<<(Bc*Fc)/256, 256>>>(Emb, A_w, A_b, XN);
    // GAT layer 0
    k_lin64<<<Nn/64, 256>>>(XN, g0_Wl, g0_bl, g0_Wr, g0_br, XL, XR);
    k_gat<<<1024, 128>>>(XL, XR, g0_att, g0_bias, G0);
    // GAT layer 1
    k_lin64<<<Nn/64, 256>>>(G0, g1_Wl, g1_bl, g1_Wr, g1_br, XL, XR);
    k_gat<<<1024, 128>>>(XL, XR, g1_att, g1_bias, G1);
    // fusion + capsule priors
    k_fus<<<(Nn*128)/256, 256>>>(XN, G0, G1, FUS);
    k_sgemm<<<dim3(2048/128, Nn/128), 256>>>(FUS, W_caps, nullptr, PR, 2048, 128);
    // routing + head
    k_route<<<Bc, 64>>>(PR, F_w, F_b, out);
}

// round 7
// speedup vs baseline: 1.6128x; 1.1152x over previous
#include <cuda_runtime.h>
#include <cuda_bf16.h>
#include <math.h>
#include <stdint.h>

#define Bc 128
#define Tc 32
#define Fc 2048
#define G3 6144
#define Hc 64
#define Nn 4096
#define KSPLIT 16
#define KCHUNK 128   // Fc / KSPLIT

// ---- static scratch (no cudaMalloc allowed) ----
__device__ float g_Gi[(size_t)Bc*Tc*G3];
__device__ float g_H0[Bc*Tc*Fc];
__device__ float g_Emb[Bc*Tc*Fc];
__device__ float g_hz[Tc*Fc];
__device__ float g_P[(size_t)KSPLIT*Tc*G3];
__device__ float g_XN[Nn*Hc];
__device__ float g_XL[Nn*Hc];
__device__ float g_XR[Nn*Hc];
__device__ float g_G0[Nn*Hc];
__device__ float g_G1[Nn*Hc];
__device__ float g_FUS[Nn*2*Hc];
__device__ float g_PR[(size_t)Nn*2048];

// bf16 hi/lo split buffers
__device__ __nv_bfloat16 g_Xhi[Bc*Tc*Fc],  g_Xlo[Bc*Tc*Fc];
__device__ __nv_bfloat16 g_H0hi[Bc*Tc*Fc], g_H0lo[Bc*Tc*Fc];
__device__ __nv_bfloat16 g_Ehi[Bc*Tc*Fc],  g_Elo[Bc*Tc*Fc];
__device__ __nv_bfloat16 g_hzb[Tc*Fc];   // zeros (used for both hi and lo)
__device__ __nv_bfloat16 g_Wih0h[(size_t)G3*Fc], g_Wih0l[(size_t)G3*Fc];
__device__ __nv_bfloat16 g_Whh0h[(size_t)G3*Fc], g_Whh0l[(size_t)G3*Fc];
__device__ __nv_bfloat16 g_Wih1h[(size_t)G3*Fc], g_Wih1l[(size_t)G3*Fc];
__device__ __nv_bfloat16 g_Whh1h[(size_t)G3*Fc], g_Whh1l[(size_t)G3*Fc];

// ---- packed f32x2 helpers (capsule GEMM only) ----
__device__ __forceinline__ unsigned long long pk2(float x){
    unsigned long long r; asm("mov.b64 %0,{%1,%1};" : "=l"(r) : "f"(x)); return r;
}
__device__ __forceinline__ void ffma2(unsigned long long& d, unsigned long long a, unsigned long long b){
    asm("fma.rn.f32x2 %0,%1,%2,%0;" : "+l"(d) : "l"(a), "l"(b));
}
__device__ __forceinline__ float2 up2(unsigned long long v){
    float2 r; asm("mov.b64 {%0,%1},%2;" : "=f"(r.x), "=f"(r.y) : "l"(v)); return r;
}

// ---- bf16 mma.sync m16n8k16 ----
__device__ __forceinline__ void mma16816(float* c, uint32_t a0, uint32_t a1, uint32_t a2, uint32_t a3,
                                         uint32_t b0, uint32_t b1){
    asm volatile("mma.sync.aligned.m16n8k16.row.col.f32.bf16.bf16.f32 "
        "{%0,%1,%2,%3}, {%4,%5,%6,%7}, {%8,%9}, {%0,%1,%2,%3};"
        : "+f"(c[0]), "+f"(c[1]), "+f"(c[2]), "+f"(c[3])
        : "r"(a0), "r"(a1), "r"(a2), "r"(a3), "r"(b0), "r"(b1));
}

// ---- utility ----
__global__ void k_zero(float* p, int n){ int i=blockIdx.x*256+threadIdx.x; if(i<n) p[i]=0.f; }
__global__ void k_zerob(__nv_bfloat16* p, int n){ int i=blockIdx.x*256+threadIdx.x; if(i<n) p[i]=__float2bfloat16(0.f); }

__device__ __forceinline__ void split1(float v, __nv_bfloat16& h, __nv_bfloat16& l){
    h = __float2bfloat16(v);
    l = __float2bfloat16(v - __bfloat162float(h));
}

__global__ void k_sansplit(const float* __restrict__ in, __nv_bfloat16* __restrict__ hi,
                           __nv_bfloat16* __restrict__ lo, int n){
    int i = blockIdx.x*256 + threadIdx.x;
    if(i<n){
        float v = in[i];
        if (isnan(v)) v = 0.f;
        else if (isinf(v)) v = (v>0.f) ? 1.0f : -3.3e38f;
        split1(v, hi[i], lo[i]);
    }
}

__global__ void k_wsplit(const float* __restrict__ W, __nv_bfloat16* __restrict__ hi,
                         __nv_bfloat16* __restrict__ lo, int n){
    int i = blockIdx.x*256 + threadIdx.x;
    if(i<n) split1(W[i], hi[i], lo[i]);
}

// ---- split-bf16 tensor-core GEMM ----
// C[m0+32, n0+256] (partial over K slice) = A @ B^T, A=[M][K] hi/lo bf16, B=[N][K] hi/lo bf16.
// grid (N/256, M/32, ksplit), block 256 (8 warps, 32 cols each). No smem.
__global__ void __launch_bounds__(256) k_mma(const __nv_bfloat16* __restrict__ Ahi,
                                             const __nv_bfloat16* __restrict__ Alo,
                                             const __nv_bfloat16* __restrict__ Bhi,
                                             const __nv_bfloat16* __restrict__ Blo,
                                             float* __restrict__ Cout,
                                             const float* __restrict__ bias,
                                             int K, int kchunk, int Ncols, int sliceStride)
{
    const int lane = threadIdx.x & 31;
    const int warp = threadIdx.x >> 5;
    const int gid = lane >> 2, tq = lane & 3;
    const int m0 = blockIdx.y * 32;
    const int n0 = blockIdx.x * 256 + warp * 32;
    const int kb0 = blockIdx.z * kchunk;

    float acc[2][4][4];
    #pragma unroll
    for(int mt=0;mt<2;mt++)
        #pragma unroll
        for(int nt=0;nt<4;nt++)
            #pragma unroll
            for(int q=0;q<4;q++) acc[mt][nt][q]=0.f;

    #pragma unroll 1
    for(int ks=0; ks<kchunk; ks+=16){
        const int kb = kb0 + ks;
        uint32_t ah[2][4], al[2][4];
        #pragma unroll
        for(int mt=0;mt<2;mt++){
            const __nv_bfloat16* p0 = Ahi + (size_t)(m0 + mt*16 + gid)*K + kb + tq*2;
            const __nv_bfloat16* p1 = p0 + (size_t)8*K;
            ah[mt][0]=*(const uint32_t*)p0;     ah[mt][2]=*(const uint32_t*)(p0+8);
            ah[mt][1]=*(const uint32_t*)p1;     ah[mt][3]=*(const uint32_t*)(p1+8);
            const __nv_bfloat16* q0 = Alo + (size_t)(m0 + mt*16 + gid)*K + kb + tq*2;
            const __nv_bfloat16* q1 = q0 + (size_t)8*K;
            al[mt][0]=*(const uint32_t*)q0;     al[mt][2]=*(const uint32_t*)(q0+8);
            al[mt][1]=*(const uint32_t*)q1;     al[mt][3]=*(const uint32_t*)(q1+8);
        }
        #pragma unroll
        for(int nt=0;nt<4;nt++){
            const __nv_bfloat16* bp = Bhi + (size_t)(n0 + nt*8 + gid)*K + kb + tq*2;
            uint32_t bh0=*(const uint32_t*)bp, bh1=*(const uint32_t*)(bp+8);
            const __nv_bfloat16* bq = Blo + (size_t)(n0 + nt*8 + gid)*K + kb + tq*2;
            uint32_t bl0=*(const uint32_t*)bq, bl1=*(const uint32_t*)(bq+8);
            #pragma unroll
            for(int mt=0;mt<2;mt++){
                mma16816(acc[mt][nt], ah[mt][0],ah[mt][1],ah[mt][2],ah[mt][3], bh0, bh1);
                mma16816(acc[mt][nt], al[mt][0],al[mt][1],al[mt][2],al[mt][3], bh0, bh1);
                mma16816(acc[mt][nt], ah[mt][0],ah[mt][1],ah[mt][2],ah[mt][3], bl0, bl1);
            }
        }
    }

    float* Cb = Cout + (size_t)blockIdx.z * sliceStride;
    #pragma unroll
    for(int mt=0;mt<2;mt++){
        #pragma unroll
        for(int nt=0;nt<4;nt++){
            int row = m0 + mt*16 + gid;
            int col = n0 + nt*8 + tq*2;
            float b0 = bias ? bias[col]   : 0.f;
            float b1 = bias ? bias[col+1] : 0.f;
            float2 v0 = {acc[mt][nt][0] + b0, acc[mt][nt][1] + b1};
            float2 v1 = {acc[mt][nt][2] + b0, acc[mt][nt][3] + b1};
            *(float2*)&Cb[(size_t)row*Ncols + col]     = v0;
            *(float2*)&Cb[(size_t)(row+8)*Ncols + col] = v1;
        }
    }
}

// ---- f32 SGEMM (capsule priors only): C = A(MxK)@B(NxK)^T, 128x128 tile ----
__global__ void __launch_bounds__(256) k_sgemm(const float* __restrict__ A,
                                               const float* __restrict__ Bm,
                                               const float* __restrict__ bias,
                                               float* __restrict__ C,
                                               int Ncols, int K)
{
    __shared__ float As[8][128];
    __shared__ float Bs[8][128];
    const int tid = threadIdx.x;
    const int tx = tid & 15, ty = tid >> 4;
    const int m0 = blockIdx.y*128, n0 = blockIdx.x*128;
    const int lr = tid >> 1, lc = (tid & 1)*4;
    const float* Ap = A + (size_t)(m0+lr)*K + lc;
    const float* Bp = Bm + (size_t)(n0+lr)*K + lc;

    unsigned long long acc[8][4];
    #pragma unroll
    for(int i=0;i<8;i++)
        #pragma unroll
        for(int j=0;j<4;j++) acc[i][j]=0ULL;

    for(int k0=0;k0<K;k0+=8){
        float4 av = *(const float4*)(Ap + k0);
        float4 bv = *(const float4*)(Bp + k0);
        __syncthreads();
        As[lc+0][lr]=av.x; As[lc+1][lr]=av.y; As[lc+2][lr]=av.z; As[lc+3][lr]=av.w;
        Bs[lc+0][lr]=bv.x; Bs[lc+1][lr]=bv.y; Bs[lc+2][lr]=bv.z; Bs[lc+3][lr]=bv.w;
        __syncthreads();
        #pragma unroll
        for(int k=0;k<8;k++){
            float4 a0 = *(const float4*)&As[k][ty*8];
            float4 a1 = *(const float4*)&As[k][ty*8+4];
            ulonglong2 b01 = *(const ulonglong2*)&Bs[k][tx*8];
            ulonglong2 b23 = *(const ulonglong2*)&Bs[k][tx*8+4];
            unsigned long long aa[8];
            aa[0]=pk2(a0.x); aa[1]=pk2(a0.y); aa[2]=pk2(a0.z); aa[3]=pk2(a0.w);
            aa[4]=pk2(a1.x); aa[5]=pk2(a1.y); aa[6]=pk2(a1.z); aa[7]=pk2(a1.w);
            #pragma unroll
            for(int i=0;i<8;i++){
                ffma2(acc[i][0], aa[i], b01.x);
                ffma2(acc[i][1], aa[i], b01.y);
                ffma2(acc[i][2], aa[i], b23.x);
                ffma2(acc[i][3], aa[i], b23.y);
            }
        }
    }
    #pragma unroll
    for(int i=0;i<8;i++){
        int row = m0 + ty*8 + i;
        #pragma unroll
        for(int j=0;j<4;j++){
            float2 v = up2(acc[i][j]);
            int col = n0 + tx*8 + j*2;
            float b0 = bias ? bias[col]   : 0.f;
            float b1 = bias ? bias[col+1] : 0.f;
            C[(size_t)row*Ncols + col]   = v.x + b0;
            C[(size_t)row*Ncols + col+1] = v.y + b1;
        }
    }
}

// ---- GRU gate fuse: combine K-split partials + input gates + biases; emit f32 + hi/lo bf16 ----
__global__ void __launch_bounds__(256) k_gate(int b,
                                              const float* __restrict__ P,
                                              const float* __restrict__ Gi,
                                              const float* __restrict__ bhh,
                                              const float* __restrict__ Hprev,
                                              float* __restrict__ Hall,
                                              __nv_bfloat16* __restrict__ Hhi,
                                              __nv_bfloat16* __restrict__ Hlo)
{
    int i4 = blockIdx.x*256 + threadIdx.x;   // 16384 quads = 32*2048/4
    int row = i4 >> 9, j = (i4 & 511)*4;
    float4 gr = {0,0,0,0}, gz = {0,0,0,0}, gn = {0,0,0,0};
    #pragma unroll 8
    for(int ks=0;ks<KSPLIT;ks++){
        const float* p = P + ((size_t)ks*Tc + row)*G3;
        float4 a = *(const float4*)(p + j);
        float4 bv = *(const float4*)(p + 2048 + j);
        float4 c = *(const float4*)(p + 4096 + j);
        gr.x+=a.x; gr.y+=a.y; gr.z+=a.z; gr.w+=a.w;
        gz.x+=bv.x; gz.y+=bv.y; gz.z+=bv.z; gz.w+=bv.w;
        gn.x+=c.x; gn.y+=c.y; gn.z+=c.z; gn.w+=c.w;
    }
    const float* gi = Gi + ((size_t)b*Tc + row)*G3;
    float4 gir = *(const float4*)(gi + j);
    float4 giz = *(const float4*)(gi + 2048 + j);
    float4 gin = *(const float4*)(gi + 4096 + j);
    float4 br = *(const float4*)(bhh + j);
    float4 bz = *(const float4*)(bhh + 2048 + j);
    float4 bn = *(const float4*)(bhh + 4096 + j);
    float4 hp = *(const float4*)(Hprev + (size_t)row*Fc + j);
    float4 ho;
    {
        float r = 1.f/(1.f + expf(-(gir.x + gr.x + br.x)));
        float z = 1.f/(1.f + expf(-(giz.x + gz.x + bz.x)));
        float n = tanhf(gin.x + r*(gn.x + bn.x));
        ho.x = (1.f - z)*n + z*hp.x;
        r = 1.f/(1.f + expf(-(gir.y + gr.y + br.y)));
        z = 1.f/(1.f + expf(-(giz.y + gz.y + bz.y)));
        n = tanhf(gin.y + r*(gn.y + bn.y));
        ho.y = (1.f - z)*n + z*hp.y;
        r = 1.f/(1.f + expf(-(gir.z + gr.z + br.z)));
        z = 1.f/(1.f + expf(-(giz.z + gz.z + bz.z)));
        n = tanhf(gin.z + r*(gn.z + bn.z));
        ho.z = (1.f - z)*n + z*hp.z;
        r = 1.f/(1.f + expf(-(gir.w + gr.w + br.w)));
        z = 1.f/(1.f + expf(-(giz.w + gz.w + bz.w)));
        n = tanhf(gin.w + r*(gn.w + bn.w));
        ho.w = (1.f - z)*n + z*hp.w;
    }
    size_t base = ((size_t)b*Tc + row)*Fc + j;
    *(float4*)(Hall + base) = ho;
    __nv_bfloat16 h0,l0,h1,l1,h2,l2,h3,l3;
    split1(ho.x,h0,l0); split1(ho.y,h1,l1); split1(ho.z,h2,l2); split1(ho.w,h3,l3);
    __nv_bfloat162 hi01; hi01.x=h0; hi01.y=h1;
    __nv_bfloat162 hi23; hi23.x=h2; hi23.y=h3;
    __nv_bfloat162 lo01; lo01.x=l0; lo01.y=l1;
    __nv_bfloat162 lo23; lo23.x=l2; lo23.y=l3;
    *(__nv_bfloat162*)(Hhi + base)     = hi01;
    *(__nv_bfloat162*)(Hhi + base + 2) = hi23;
    *(__nv_bfloat162*)(Hlo + base)     = lo01;
    *(__nv_bfloat162*)(Hlo + base + 2) = lo23;
}

// ---- temporal attention over T=32 per (b,f) ----
__global__ void __launch_bounds__(256) k_attn(const float* __restrict__ Emb,
                                              const float* __restrict__ Aw,
                                              const float* __restrict__ Ab,
                                              float* __restrict__ XN)
{
    __shared__ float sW[32][33];
    __shared__ float sB[32];
    int tid = threadIdx.x;
    for(int i=tid;i<1024;i+=256) sW[i>>5][i&31] = Aw[i];
    if(tid<32) sB[tid]=Ab[tid];
    __syncthreads();
    int g = blockIdx.x*256 + tid;        // b*2048 + f
    int b = g >> 11, f = g & 2047;
    float tA[32];
    #pragma unroll
    for(int t=0;t<32;t++) tA[t] = tanhf(Emb[((size_t)b*32 + t)*Fc + f]);
    float mx = -1e30f, aw[32];
    #pragma unroll
    for(int t2=0;t2<32;t2++){
        float s = sB[t2];
        #pragma unroll
        for(int t=0;t<32;t++) s += tA[t]*sW[t2][t];
        aw[t2]=s; mx = fmaxf(mx, s);
    }
    float den=0.f, num=0.f;
    #pragma unroll
    for(int t=0;t<32;t++){ float e = expf(aw[t]-mx); den += e; num += e*tA[t]; }
    XN[g] = tanhf(num/den);
}

// ---- GAT projections: XL = X@Wl^T+bl, XR = X@Wr^T+br (64x64) ----
__global__ void __launch_bounds__(256) k_lin64(const float* __restrict__ X,
                                               const float* __restrict__ Wl, const float* __restrict__ bl,
                                               const float* __restrict__ Wr, const float* __restrict__ br,
                                               float* __restrict__ XL, float* __restrict__ XR)
{
    __shared__ float sX[64][65];
    __shared__ float sW[64][65];
    int tid = threadIdx.x;
    int r0 = blockIdx.x*64;
    for(int i=tid;i<4096;i+=256){ int r=i>>6, c=i&63; sX[r][c]=X[(size_t)(r0+r)*64+c]; }
    for(int i=tid;i<4096;i+=256){ int r=i>>6, c=i&63; sW[r][c]=Wl[i]; }
    __syncthreads();
    int r = tid & 63, cq = tid >> 6;
    #pragma unroll 4
    for(int cc=0; cc<16; cc++){
        int c = cq*16 + cc;
        float s = bl[c];
        #pragma unroll
        for(int k=0;k<64;k++) s += sX[r][k]*sW[c][k];
        XL[(size_t)(r0+r)*64 + c] = s;
    }
    __syncthreads();
    for(int i=tid;i<4096;i+=256){ int rr=i>>6, c=i&63; sW[rr][c]=Wr[i]; }
    __syncthreads();
    #pragma unroll 4
    for(int cc=0; cc<16; cc++){
        int c = cq*16 + cc;
        float s = br[c];
        #pragma unroll
        for(int k=0;k<64;k++) s += sX[r][k]*sW[c][k];
        XR[(size_t)(r0+r)*64 + c] = s;
    }
}

// ---- GATv2 on dense 32x32 block graph; one warp per dst node; tanh output ----
__global__ void __launch_bounds__(128) k_gat(const float* __restrict__ XL,
                                             const float* __restrict__ XR,
                                             const float* __restrict__ att,
                                             const float* __restrict__ bias,
                                             float* __restrict__ OUT)
{
    int w = threadIdx.x >> 5, lane = threadIdx.x & 31;
    int g = blockIdx.x >> 3;
    int d = ((blockIdx.x & 7) << 2) + w;
    int nd = g*32 + d;
    float xr0 = XR[(size_t)nd*64 + lane];
    float xr1 = XR[(size_t)nd*64 + 32 + lane];
    float a0 = att[lane], a1 = att[lane+32];
    const float* xlg = XL + (size_t)g*32*64;
    float lg[32];
    #pragma unroll
    for(int s=0;s<32;s++){
        float u = xlg[s*64 + lane]      + xr0;
        float v = xlg[s*64 + 32 + lane] + xr1;
        u = u>0.f ? u : 0.2f*u;
        v = v>0.f ? v : 0.2f*v;
        float t = u*a0 + v*a1;
        #pragma unroll
        for(int o=16;o>0;o>>=1) t += __shfl_xor_sync(0xffffffffu, t, o);
        lg[s] = t;
    }
    float m = -1e30f;
    #pragma unroll
    for(int s=0;s<32;s++) m = fmaxf(m, lg[s]);
    float den = 0.f;
    #pragma unroll
    for(int s=0;s<32;s++){ lg[s] = expf(lg[s]-m); den += lg[s]; }
    float inv = 1.f/den, o0=0.f, o1=0.f;
    #pragma unroll
    for(int s=0;s<32;s++){
        float al = lg[s]*inv;
        o0 += al * xlg[s*64 + lane];
        o1 += al * xlg[s*64 + 32 + lane];
    }
    OUT[(size_t)nd*64 + lane]      = tanhf(o0 + bias[lane]);
    OUT[(size_t)nd*64 + 32 + lane] = tanhf(o1 + bias[lane+32]);
}

// ---- fusion concat ----
__global__ void k_fus(const float* __restrict__ XN, const float* __restrict__ G0,
                      const float* __restrict__ G1, float* __restrict__ FUS)
{
    int i = blockIdx.x*256 + threadIdx.x;  // 4096*128
    int n = i >> 7, q = i & 127;
    FUS[i] = (q < 64) ? XN[(size_t)n*64 + q]
                      : (G0[(size_t)n*64 + q-64] + G1[(size_t)n*64 + q-64]);
}

// ---- capsule routing (3 iters) + final head ----
__global__ void __launch_bounds__(64) k_route(const float* __restrict__ PR,
                                              const float* __restrict__ Fw,
                                              const float* __restrict__ Fb,
                                              float* __restrict__ out)
{
    int n = blockIdx.x, l = threadIdx.x;
    const float* base = PR + (size_t)n*65536 + l;   // idx: c*2048 + o*64
    float o0[32], o1[32], pc[32], te[32];
    #pragma unroll
    for(int o=0;o<32;o++) o0[o]=0.f;
    for(int c=0;c<32;c++){
        const float* pcol = base + (size_t)c*2048;
        #pragma unroll
        for(int o=0;o<32;o++) o0[o] += pcol[o*64];
    }
    #pragma unroll
    for(int o=0;o<32;o++){ o0[o] *= (1.f/32.f); o1[o]=0.f; }
    for(int c=0;c<32;c++){
        const float* pcol = base + (size_t)c*2048;
        float m = -1e30f;
        #pragma unroll
        for(int o=0;o<32;o++){ pc[o]=pcol[o*64]; float lgv = pc[o]*o0[o]; te[o]=lgv; m = fmaxf(m,lgv); }
        float den=0.f;
        #pragma unroll
        for(int o=0;o<32;o++){ te[o]=expf(te[o]-m); den+=te[o]; }
        float inv = 1.f/den;
        #pragma unroll
        for(int o=0;o<32;o++) o1[o] += te[o]*inv*pc[o];
    }
    #pragma unroll
    for(int o=0;o<32;o++){ o0[o] += o1[o]; o1[o]=0.f; }
    for(int c=0;c<32;c++){
        const float* pcol = base + (size_t)c*2048;
        float m = -1e30f;
        #pragma unroll
        for(int o=0;o<32;o++){ pc[o]=pcol[o*64]; float lgv = pc[o]*o0[o]; te[o]=lgv; m = fmaxf(m,lgv); }
        float den=0.f;
        #pragma unroll
        for(int o=0;o<32;o++){ te[o]=expf(te[o]-m); den+=te[o]; }
        float inv = 1.f/den;
        #pragma unroll
        for(int o=0;o<32;o++) o1[o] += te[o]*inv*pc[o];
    }
    __shared__ float sc[32][65];
    #pragma unroll
    for(int o=0;o<32;o++) sc[o][l] = tanhf(o1[o]);
    __syncthreads();
    for(int q=0;q<16;q++){
        int idx = l*16 + q;
        int o = idx >> 5, d2 = idx & 31;
        float s = Fb[d2];
        #pragma unroll
        for(int ll=0;ll<64;ll++) s += sc[o][ll]*Fw[d2*64+ll];
        out[(size_t)n*1024 + o*32 + d2] = tanhf(s);
    }
}

extern "C" void kernel_launch(void* const* d_in, const int* in_sizes, int n_in,
                              void* d_out, int out_size)
{
    const float* inputs = (const float*)d_in[0];
    const float* Wih0 = (const float*)d_in[1];
    const float* Whh0 = (const float*)d_in[2];
    const float* bih0 = (const float*)d_in[3];
    const float* bhh0 = (const float*)d_in[4];
    const float* Wih1 = (const float*)d_in[5];
    const float* Whh1 = (const float*)d_in[6];
    const float* bih1 = (const float*)d_in[7];
    const float* bhh1 = (const float*)d_in[8];
    const float* A_w  = (const float*)d_in[9];
    const float* A_b  = (const float*)d_in[10];
    const float* g0_Wl = (const float*)d_in[11];
    const float* g0_bl = (const float*)d_in[12];
    const float* g0_Wr = (const float*)d_in[13];
    const float* g0_br = (const float*)d_in[14];
    const float* g0_att = (const float*)d_in[15];
    const float* g0_bias = (const float*)d_in[16];
    const float* g1_Wl = (const float*)d_in[17];
    const float* g1_bl = (const float*)d_in[18];
    const float* g1_Wr = (const float*)d_in[19];
    const float* g1_br = (const float*)d_in[20];
    const float* g1_att = (const float*)d_in[21];
    const float* g1_bias = (const float*)d_in[22];
    const float* W_caps = (const float*)d_in[23];
    const float* F_w = (const float*)d_in[24];
    const float* F_b = (const float*)d_in[25];
    float* out = (float*)d_out;

    float *Gi,*H0,*Emb,*hz,*P,*XN,*XL,*XR,*G0,*G1,*FUS,*PR;
    __nv_bfloat16 *Xhi,*Xlo,*H0hi,*H0lo,*Ehi,*Elo,*hzb;
    __nv_bfloat16 *Wih0h,*Wih0l,*Whh0h,*Whh0l,*Wih1h,*Wih1l,*Whh1h,*Whh1l;
    cudaGetSymbolAddress((void**)&Gi,  g_Gi);
    cudaGetSymbolAddress((void**)&H0,  g_H0);
    cudaGetSymbolAddress((void**)&Emb, g_Emb);
    cudaGetSymbolAddress((void**)&hz,  g_hz);
    cudaGetSymbolAddress((void**)&P,   g_P);
    cudaGetSymbolAddress((void**)&XN,  g_XN);
    cudaGetSymbolAddress((void**)&XL,  g_XL);
    cudaGetSymbolAddress((void**)&XR,  g_XR);
    cudaGetSymbolAddress((void**)&G0,  g_G0);
    cudaGetSymbolAddress((void**)&G1,  g_G1);
    cudaGetSymbolAddress((void**)&FUS, g_FUS);
    cudaGetSymbolAddress((void**)&PR,  g_PR);
    cudaGetSymbolAddress((void**)&Xhi, g_Xhi);  cudaGetSymbolAddress((void**)&Xlo, g_Xlo);
    cudaGetSymbolAddress((void**)&H0hi,g_H0hi); cudaGetSymbolAddress((void**)&H0lo,g_H0lo);
    cudaGetSymbolAddress((void**)&Ehi, g_Ehi);  cudaGetSymbolAddress((void**)&Elo, g_Elo);
    cudaGetSymbolAddress((void**)&hzb, g_hzb);
    cudaGetSymbolAddress((void**)&Wih0h, g_Wih0h); cudaGetSymbolAddress((void**)&Wih0l, g_Wih0l);
    cudaGetSymbolAddress((void**)&Whh0h, g_Whh0h); cudaGetSymbolAddress((void**)&Whh0l, g_Whh0l);
    cudaGetSymbolAddress((void**)&Wih1h, g_Wih1h); cudaGetSymbolAddress((void**)&Wih1l, g_Wih1l);
    cudaGetSymbolAddress((void**)&Whh1h, g_Whh1h); cudaGetSymbolAddress((void**)&Whh1l, g_Whh1l);

    const int NTOT = Bc*Tc*Fc;           // 8.4M
    const int WTOT = G3*Fc;              // 12.58M
    k_zero<<<(Tc*Fc+255)/256, 256>>>(hz, Tc*Fc);
    k_zerob<<<(Tc*Fc+255)/256, 256>>>(hzb, Tc*Fc);
    k_sansplit<<<(NTOT+255)/256, 256>>>(inputs, Xhi, Xlo, NTOT);
    k_wsplit<<<(WTOT+255)/256, 256>>>(Wih0, Wih0h, Wih0l, WTOT);
    k_wsplit<<<(WTOT+255)/256, 256>>>(Whh0, Whh0h, Whh0l, WTOT);
    k_wsplit<<<(WTOT+255)/256, 256>>>(Wih1, Wih1h, Wih1l, WTOT);
    k_wsplit<<<(WTOT+255)/256, 256>>>(Whh1, Whh1h, Whh1l, WTOT);

    // layer 0: input-gate GEMM (full K, bias bih0) then recurrent scan
    k_mma<<<dim3(G3/256, (Bc*Tc)/32, 1), 256>>>(Xhi, Xlo, Wih0h, Wih0l, Gi, bih0, Fc, Fc, G3, 0);
    for(int b=0;b<Bc;b++){
        const __nv_bfloat16* ahi = b ? (H0hi + (size_t)(b-1)*Tc*Fc) : hzb;
        const __nv_bfloat16* alo = b ? (H0lo + (size_t)(b-1)*Tc*Fc) : hzb;
        const float* hp = b ? (H0 + (size_t)(b-1)*Tc*Fc) : hz;
        k_mma<<<dim3(G3/256, 1, KSPLIT), 256>>>(ahi, alo, Whh0h, Whh0l, P, nullptr, Fc, KCHUNK, G3, Tc*G3);
        k_gate<<<64, 256>>>(b, P, Gi, bhh0, hp, H0, H0hi, H0lo);
    }
    // layer 1
    k_mma<<<dim3(G3/256, (Bc*Tc)/32, 1), 256>>>(H0hi, H0lo, Wih1h, Wih1l, Gi, bih1, Fc, Fc, G3, 0);
    for(int b=0;b<Bc;b++){
        const __nv_bfloat16* ahi = b ? (Ehi + (size_t)(b-1)*Tc*Fc) : hzb;
        const __nv_bfloat16* alo = b ? (Elo + (size_t)(b-1)*Tc*Fc) : hzb;
        const float* hp = b ? (Emb + (size_t)(b-1)*Tc*Fc) : hz;
        k_mma<<<dim3(G3/256, 1, KSPLIT), 256>>>(ahi, alo, Whh1h, Whh1l, P, nullptr, Fc, KCHUNK, G3, Tc*G3);
        k_gate<<<64, 256>>>(b, P, Gi, bhh1, hp, Emb, Ehi, Elo);
    }
    // attention -> node features
    k_attn<<<(Bc*Fc)/256, 256>>>(Emb, A_w, A_b, XN);
    // GAT layer 0
    k_lin64<<<Nn/64, 256>>>(XN, g0_Wl, g0_bl, g0_Wr, g0_br, XL, XR);
    k_gat<<<1024, 128>>>(XL, XR, g0_att, g0_bias, G0);
    // GAT layer 1
    k_lin64<<<Nn/64, 256>>>(G0, g1_Wl, g1_bl, g1_Wr, g1_br, XL, XR);
    k_gat<<<1024, 128>>>(XL, XR, g1_att, g1_bias, G1);
    // fusion + capsule priors
    k_fus<<<(Nn*128)/256, 256>>>(XN, G0, G1, FUS);
    k_sgemm<<<dim3(2048/128, Nn/128), 256>>>(FUS, W_caps, nullptr, PR, 2048, 128);
    // routing + head
    k_route<<<Bc, 64>>>(PR, F_w, F_b, out);
}

// round 8
// speedup vs baseline: 1.6417x; 1.0179x over previous
#include <cuda_runtime.h>
#include <cuda_bf16.h>
#include <math.h>
#include <stdint.h>

#define Bc 128
#define Tc 32
#define Fc 2048
#define G3 6144
#define Hc 64
#define Nn 4096
#define KSPLIT 16
#define KCHUNK 128   // Fc / KSPLIT

// ---- static scratch (no cudaMalloc allowed) ----
__device__ float g_Gi[(size_t)Bc*Tc*G3];
__device__ float g_H0[Bc*Tc*Fc];
__device__ float g_Emb[Bc*Tc*Fc];
__device__ float g_hz[Tc*Fc];
__device__ float g_P[(size_t)KSPLIT*Tc*G3];
__device__ float g_XN[Nn*Hc];
__device__ float g_XL[Nn*Hc];
__device__ float g_XR[Nn*Hc];
__device__ float g_G0[Nn*Hc];
__device__ float g_G1[Nn*Hc];
__device__ float g_FUS[Nn*2*Hc];
__device__ float g_PR[(size_t)Nn*2048];

// bf16 hi/lo split buffers
__device__ __nv_bfloat16 g_Xhi[Bc*Tc*Fc],  g_Xlo[Bc*Tc*Fc];
__device__ __nv_bfloat16 g_H0hi[Bc*Tc*Fc], g_H0lo[Bc*Tc*Fc];
__device__ __nv_bfloat16 g_Ehi[Bc*Tc*Fc],  g_Elo[Bc*Tc*Fc];
__device__ __nv_bfloat16 g_hzb[Tc*Fc];   // zeros (used for both hi and lo)
__device__ __nv_bfloat16 g_Wih0h[(size_t)G3*Fc], g_Wih0l[(size_t)G3*Fc];
__device__ __nv_bfloat16 g_Whh0h[(size_t)G3*Fc], g_Whh0l[(size_t)G3*Fc];
__device__ __nv_bfloat16 g_Wih1h[(size_t)G3*Fc], g_Wih1l[(size_t)G3*Fc];
__device__ __nv_bfloat16 g_Whh1h[(size_t)G3*Fc], g_Whh1l[(size_t)G3*Fc];

// ---- packed f32x2 helpers (capsule GEMM only) ----
__device__ __forceinline__ unsigned long long pk2(float x){
    unsigned long long r; asm("mov.b64 %0,{%1,%1};" : "=l"(r) : "f"(x)); return r;
}
__device__ __forceinline__ void ffma2(unsigned long long& d, unsigned long long a, unsigned long long b){
    asm("fma.rn.f32x2 %0,%1,%2,%0;" : "+l"(d) : "l"(a), "l"(b));
}
__device__ __forceinline__ float2 up2(unsigned long long v){
    float2 r; asm("mov.b64 {%0,%1},%2;" : "=f"(r.x), "=f"(r.y) : "l"(v)); return r;
}

// ---- bf16 mma.sync m16n8k16 ----
__device__ __forceinline__ void mma16816(float* c, uint32_t a0, uint32_t a1, uint32_t a2, uint32_t a3,
                                         uint32_t b0, uint32_t b1){
    asm volatile("mma.sync.aligned.m16n8k16.row.col.f32.bf16.bf16.f32 "
        "{%0,%1,%2,%3}, {%4,%5,%6,%7}, {%8,%9}, {%0,%1,%2,%3};"
        : "+f"(c[0]), "+f"(c[1]), "+f"(c[2]), "+f"(c[3])
        : "r"(a0), "r"(a1), "r"(a2), "r"(a3), "r"(b0), "r"(b1));
}

__device__ __forceinline__ uint32_t ld32(const __nv_bfloat16* p){ return *(const uint32_t*)p; }

// ---- utility ----
__global__ void k_zero(float* p, int n){ int i=blockIdx.x*256+threadIdx.x; if(i<n) p[i]=0.f; }
__global__ void k_zerob(__nv_bfloat16* p, int n){ int i=blockIdx.x*256+threadIdx.x; if(i<n) p[i]=__float2bfloat16(0.f); }

__device__ __forceinline__ void split1(float v, __nv_bfloat16& h, __nv_bfloat16& l){
    h = __float2bfloat16(v);
    l = __float2bfloat16(v - __bfloat162float(h));
}
__device__ __forceinline__ float san1(float v){
    if (isnan(v)) return 0.f;
    if (isinf(v)) return (v>0.f) ? 1.0f : -3.3e38f;
    return v;
}

__global__ void k_sansplit4(const float4* __restrict__ in, __nv_bfloat162* __restrict__ hi,
                            __nv_bfloat162* __restrict__ lo, int n4){
    int i = blockIdx.x*256 + threadIdx.x;
    if(i<n4){
        float4 v = in[i];
        v.x=san1(v.x); v.y=san1(v.y); v.z=san1(v.z); v.w=san1(v.w);
        __nv_bfloat16 h0,l0,h1,l1,h2,l2,h3,l3;
        split1(v.x,h0,l0); split1(v.y,h1,l1); split1(v.z,h2,l2); split1(v.w,h3,l3);
        __nv_bfloat162 a,b,c,d; a.x=h0;a.y=h1; b.x=h2;b.y=h3; c.x=l0;c.y=l1; d.x=l2;d.y=l3;
        hi[2*i]=a; hi[2*i+1]=b; lo[2*i]=c; lo[2*i+1]=d;
    }
}

__global__ void k_wsplit4(const float4* __restrict__ W, __nv_bfloat162* __restrict__ hi,
                          __nv_bfloat162* __restrict__ lo, int n4){
    int i = blockIdx.x*256 + threadIdx.x;
    if(i<n4){
        float4 v = W[i];
        __nv_bfloat16 h0,l0,h1,l1,h2,l2,h3,l3;
        split1(v.x,h0,l0); split1(v.y,h1,l1); split1(v.z,h2,l2); split1(v.w,h3,l3);
        __nv_bfloat162 a,b,c,d; a.x=h0;a.y=h1; b.x=h2;b.y=h3; c.x=l0;c.y=l1; d.x=l2;d.y=l3;
        hi[2*i]=a; hi[2*i+1]=b; lo[2*i]=c; lo[2*i+1]=d;
    }
}

// ---- split-bf16 tensor-core GEMM, register-double-buffered ----
// C[32 x 128-tile] (partial over K slice) = A @ B^T; A[M][K], B[N][K] hi/lo bf16.
// grid (Ncols/128, M/32, ksplit), block 128 (4 warps x 32 cols).
#define LOADK(I, KB) do{ \
    const __nv_bfloat16 *pa0 = Ahi + aoff + (KB); \
    const __nv_bfloat16 *qa0 = Alo + aoff + (KB); \
    const __nv_bfloat16 *pb0 = Bhi + boff + (KB); \
    const __nv_bfloat16 *qb0 = Blo + boff + (KB); \
    ah[I][0][0]=ld32(pa0);          ah[I][0][2]=ld32(pa0+8); \
    ah[I][0][1]=ld32(pa0+8*Ks);     ah[I][0][3]=ld32(pa0+8*Ks+8); \
    ah[I][1][0]=ld32(pa0+16*Ks);    ah[I][1][2]=ld32(pa0+16*Ks+8); \
    ah[I][1][1]=ld32(pa0+24*Ks);    ah[I][1][3]=ld32(pa0+24*Ks+8); \
    al[I][0][0]=ld32(qa0);          al[I][0][2]=ld32(qa0+8); \
    al[I][0][1]=ld32(qa0+8*Ks);     al[I][0][3]=ld32(qa0+8*Ks+8); \
    al[I][1][0]=ld32(qa0+16*Ks);    al[I][1][2]=ld32(qa0+16*Ks+8); \
    al[I][1][1]=ld32(qa0+24*Ks);    al[I][1][3]=ld32(qa0+24*Ks+8); \
    bh[I][0][0]=ld32(pb0);          bh[I][0][1]=ld32(pb0+8); \
    bh[I][1][0]=ld32(pb0+8*Ks);     bh[I][1][1]=ld32(pb0+8*Ks+8); \
    bh[I][2][0]=ld32(pb0+16*Ks);    bh[I][2][1]=ld32(pb0+16*Ks+8); \
    bh[I][3][0]=ld32(pb0+24*Ks);    bh[I][3][1]=ld32(pb0+24*Ks+8); \
    bl[I][0][0]=ld32(qb0);          bl[I][0][1]=ld32(qb0+8); \
    bl[I][1][0]=ld32(qb0+8*Ks);     bl[I][1][1]=ld32(qb0+8*Ks+8); \
    bl[I][2][0]=ld32(qb0+16*Ks);    bl[I][2][1]=ld32(qb0+16*Ks+8); \
    bl[I][3][0]=ld32(qb0+24*Ks);    bl[I][3][1]=ld32(qb0+24*Ks+8); \
}while(0)

#define MMAK(I) do{ \
    _Pragma("unroll") \
    for(int nt=0;nt<4;nt++){ \
        _Pragma("unroll") \
        for(int mt=0;mt<2;mt++){ \
            mma16816(acc[mt][nt], ah[I][mt][0],ah[I][mt][1],ah[I][mt][2],ah[I][mt][3], bh[I][nt][0], bh[I][nt][1]); \
            mma16816(acc[mt][nt], al[I][mt][0],al[I][mt][1],al[I][mt][2],al[I][mt][3], bh[I][nt][0], bh[I][nt][1]); \
            mma16816(acc[mt][nt], ah[I][mt][0],ah[I][mt][1],ah[I][mt][2],ah[I][mt][3], bl[I][nt][0], bl[I][nt][1]); \
        } \
    } \
}while(0)

__global__ void __launch_bounds__(128, 4) k_mma(const __nv_bfloat16* __restrict__ Ahi,
                                                const __nv_bfloat16* __restrict__ Alo,
                                                const __nv_bfloat16* __restrict__ Bhi,
                                                const __nv_bfloat16* __restrict__ Blo,
                                                float* __restrict__ Cout,
                                                const float* __restrict__ bias,
                                                int K, int kchunk, int Ncols, int sliceStride)
{
    const int lane = threadIdx.x & 31;
    const int warp = threadIdx.x >> 5;
    const int gid = lane >> 2, tq = lane & 3;
    const int m0 = blockIdx.y * 32;
    const int n0 = blockIdx.x * 128 + warp * 32;
    const int kb0 = blockIdx.z * kchunk;
    const size_t Ks = K;

    const size_t aoff = (size_t)(m0 + gid)*Ks + tq*2;
    const size_t boff = (size_t)(n0 + gid)*Ks + tq*2;

    float acc[2][4][4];
    #pragma unroll
    for(int mt=0;mt<2;mt++)
        #pragma unroll
        for(int nt=0;nt<4;nt++)
            #pragma unroll
            for(int q=0;q<4;q++) acc[mt][nt][q]=0.f;

    uint32_t ah[2][2][4], al[2][2][4], bh[2][4][2], bl[2][4][2];

    const int NT = kchunk >> 4;
    LOADK(0, kb0);
    #pragma unroll 1
    for(int t=0; t<NT; t+=2){
        if(t+1 < NT) LOADK(1, kb0 + (t+1)*16);
        MMAK(0);
        if(t+2 < NT) LOADK(0, kb0 + (t+2)*16);
        if(t+1 < NT) MMAK(1);
    }

    float* Cb = Cout + (size_t)blockIdx.z * sliceStride;
    #pragma unroll
    for(int mt=0;mt<2;mt++){
        #pragma unroll
        for(int nt=0;nt<4;nt++){
            int row = m0 + mt*16 + gid;
            int col = n0 + nt*8 + tq*2;
            float b0 = bias ? bias[col]   : 0.f;
            float b1 = bias ? bias[col+1] : 0.f;
            float2 v0 = {acc[mt][nt][0] + b0, acc[mt][nt][1] + b1};
            float2 v1 = {acc[mt][nt][2] + b0, acc[mt][nt][3] + b1};
            *(float2*)&Cb[(size_t)row*Ncols + col]     = v0;
            *(float2*)&Cb[(size_t)(row+8)*Ncols + col] = v1;
        }
    }
}

// ---- f32 SGEMM (capsule priors only): C = A(MxK)@B(NxK)^T, 128x128 tile ----
__global__ void __launch_bounds__(256) k_sgemm(const float* __restrict__ A,
                                               const float* __restrict__ Bm,
                                               const float* __restrict__ bias,
                                               float* __restrict__ C,
                                               int Ncols, int K)
{
    __shared__ float As[8][128];
    __shared__ float Bs[8][128];
    const int tid = threadIdx.x;
    const int tx = tid & 15, ty = tid >> 4;
    const int m0 = blockIdx.y*128, n0 = blockIdx.x*128;
    const int lr = tid >> 1, lc = (tid & 1)*4;
    const float* Ap = A + (size_t)(m0+lr)*K + lc;
    const float* Bp = Bm + (size_t)(n0+lr)*K + lc;

    unsigned long long acc[8][4];
    #pragma unroll
    for(int i=0;i<8;i++)
        #pragma unroll
        for(int j=0;j<4;j++) acc[i][j]=0ULL;

    for(int k0=0;k0<K;k0+=8){
        float4 av = *(const float4*)(Ap + k0);
        float4 bv = *(const float4*)(Bp + k0);
        __syncthreads();
        As[lc+0][lr]=av.x; As[lc+1][lr]=av.y; As[lc+2][lr]=av.z; As[lc+3][lr]=av.w;
        Bs[lc+0][lr]=bv.x; Bs[lc+1][lr]=bv.y; Bs[lc+2][lr]=bv.z; Bs[lc+3][lr]=bv.w;
        __syncthreads();
        #pragma unroll
        for(int k=0;k<8;k++){
            float4 a0 = *(const float4*)&As[k][ty*8];
            float4 a1 = *(const float4*)&As[k][ty*8+4];
            ulonglong2 b01 = *(const ulonglong2*)&Bs[k][tx*8];
            ulonglong2 b23 = *(const ulonglong2*)&Bs[k][tx*8+4];
            unsigned long long aa[8];
            aa[0]=pk2(a0.x); aa[1]=pk2(a0.y); aa[2]=pk2(a0.z); aa[3]=pk2(a0.w);
            aa[4]=pk2(a1.x); aa[5]=pk2(a1.y); aa[6]=pk2(a1.z); aa[7]=pk2(a1.w);
            #pragma unroll
            for(int i=0;i<8;i++){
                ffma2(acc[i][0], aa[i], b01.x);
                ffma2(acc[i][1], aa[i], b01.y);
                ffma2(acc[i][2], aa[i], b23.x);
                ffma2(acc[i][3], aa[i], b23.y);
            }
        }
    }
    #pragma unroll
    for(int i=0;i<8;i++){
        int row = m0 + ty*8 + i;
        #pragma unroll
        for(int j=0;j<4;j++){
            float2 v = up2(acc[i][j]);
            int col = n0 + tx*8 + j*2;
            float b0 = bias ? bias[col]   : 0.f;
            float b1 = bias ? bias[col+1] : 0.f;
            C[(size_t)row*Ncols + col]   = v.x + b0;
            C[(size_t)row*Ncols + col+1] = v.y + b1;
        }
    }
}

// ---- GRU gate fuse: combine K-split partials + input gates + biases; emit f32 + hi/lo bf16 ----
__global__ void __launch_bounds__(256) k_gate(int b,
                                              const float* __restrict__ P,
                                              const float* __restrict__ Gi,
                                              const float* __restrict__ bhh,
                                              const float* __restrict__ Hprev,
                                              float* __restrict__ Hall,
                                              __nv_bfloat16* __restrict__ Hhi,
                                              __nv_bfloat16* __restrict__ Hlo)
{
    int i4 = blockIdx.x*256 + threadIdx.x;   // 16384 quads = 32*2048/4
    int row = i4 >> 9, j = (i4 & 511)*4;
    float4 gr = {0,0,0,0}, gz = {0,0,0,0}, gn = {0,0,0,0};
    #pragma unroll 8
    for(int ks=0;ks<KSPLIT;ks++){
        const float* p = P + ((size_t)ks*Tc + row)*G3;
        float4 a = *(const float4*)(p + j);
        float4 bv = *(const float4*)(p + 2048 + j);
        float4 c = *(const float4*)(p + 4096 + j);
        gr.x+=a.x; gr.y+=a.y; gr.z+=a.z; gr.w+=a.w;
        gz.x+=bv.x; gz.y+=bv.y; gz.z+=bv.z; gz.w+=bv.w;
        gn.x+=c.x; gn.y+=c.y; gn.z+=c.z; gn.w+=c.w;
    }
    const float* gi = Gi + ((size_t)b*Tc + row)*G3;
    float4 gir = *(const float4*)(gi + j);
    float4 giz = *(const float4*)(gi + 2048 + j);
    float4 gin = *(const float4*)(gi + 4096 + j);
    float4 br = *(const float4*)(bhh + j);
    float4 bz = *(const float4*)(bhh + 2048 + j);
    float4 bn = *(const float4*)(bhh + 4096 + j);
    float4 hp = *(const float4*)(Hprev + (size_t)row*Fc + j);
    float4 ho;
    {
        float r = 1.f/(1.f + expf(-(gir.x + gr.x + br.x)));
        float z = 1.f/(1.f + expf(-(giz.x + gz.x + bz.x)));
        float n = tanhf(gin.x + r*(gn.x + bn.x));
        ho.x = (1.f - z)*n + z*hp.x;
        r = 1.f/(1.f + expf(-(gir.y + gr.y + br.y)));
        z = 1.f/(1.f + expf(-(giz.y + gz.y + bz.y)));
        n = tanhf(gin.y + r*(gn.y + bn.y));
        ho.y = (1.f - z)*n + z*hp.y;
        r = 1.f/(1.f + expf(-(gir.z + gr.z + br.z)));
        z = 1.f/(1.f + expf(-(giz.z + gz.z + bz.z)));
        n = tanhf(gin.z + r*(gn.z + bn.z));
        ho.z = (1.f - z)*n + z*hp.z;
        r = 1.f/(1.f + expf(-(gir.w + gr.w + br.w)));
        z = 1.f/(1.f + expf(-(giz.w + gz.w + bz.w)));
        n = tanhf(gin.w + r*(gn.w + bn.w));
        ho.w = (1.f - z)*n + z*hp.w;
    }
    size_t base = ((size_t)b*Tc + row)*Fc + j;
    *(float4*)(Hall + base) = ho;
    __nv_bfloat16 h0,l0,h1,l1,h2,l2,h3,l3;
    split1(ho.x,h0,l0); split1(ho.y,h1,l1); split1(ho.z,h2,l2); split1(ho.w,h3,l3);
    __nv_bfloat162 hi01; hi01.x=h0; hi01.y=h1;
    __nv_bfloat162 hi23; hi23.x=h2; hi23.y=h3;
    __nv_bfloat162 lo01; lo01.x=l0; lo01.y=l1;
    __nv_bfloat162 lo23; lo23.x=l2; lo23.y=l3;
    *(__nv_bfloat162*)(Hhi + base)     = hi01;
    *(__nv_bfloat162*)(Hhi + base + 2) = hi23;
    *(__nv_bfloat162*)(Hlo + base)     = lo01;
    *(__nv_bfloat162*)(Hlo + base + 2) = lo23;
}

// ---- temporal attention over T=32 per (b,f) ----
__global__ void __launch_bounds__(256) k_attn(const float* __restrict__ Emb,
                                              const float* __restrict__ Aw,
                                              const float* __restrict__ Ab,
                                              float* __restrict__ XN)
{
    __shared__ float sW[32][33];
    __shared__ float sB[32];
    int tid = threadIdx.x;
    for(int i=tid;i<1024;i+=256) sW[i>>5][i&31] = Aw[i];
    if(tid<32) sB[tid]=Ab[tid];
    __syncthreads();
    int g = blockIdx.x*256 + tid;        // b*2048 + f
    int b = g >> 11, f = g & 2047;
    float tA[32];
    #pragma unroll
    for(int t=0;t<32;t++) tA[t] = tanhf(Emb[((size_t)b*32 + t)*Fc + f]);
    float mx = -1e30f, aw[32];
    #pragma unroll
    for(int t2=0;t2<32;t2++){
        float s = sB[t2];
        #pragma unroll
        for(int t=0;t<32;t++) s += tA[t]*sW[t2][t];
        aw[t2]=s; mx = fmaxf(mx, s);
    }
    float den=0.f, num=0.f;
    #pragma unroll
    for(int t=0;t<32;t++){ float e = expf(aw[t]-mx); den += e; num += e*tA[t]; }
    XN[g] = tanhf(num/den);
}

// ---- GAT projections: XL = X@Wl^T+bl, XR = X@Wr^T+br (64x64) ----
__global__ void __launch_bounds__(256) k_lin64(const float* __restrict__ X,
                                               const float* __restrict__ Wl, const float* __restrict__ bl,
                                               const float* __restrict__ Wr, const float* __restrict__ br,
                                               float* __restrict__ XL, float* __restrict__ XR)
{
    __shared__ float sX[64][65];
    __shared__ float sW[64][65];
    int tid = threadIdx.x;
    int r0 = blockIdx.x*64;
    for(int i=tid;i<4096;i+=256){ int r=i>>6, c=i&63; sX[r][c]=X[(size_t)(r0+r)*64+c]; }
    for(int i=tid;i<4096;i+=256){ int r=i>>6, c=i&63; sW[r][c]=Wl[i]; }
    __syncthreads();
    int r = tid & 63, cq = tid >> 6;
    #pragma unroll 4
    for(int cc=0; cc<16; cc++){
        int c = cq*16 + cc;
        float s = bl[c];
        #pragma unroll
        for(int k=0;k<64;k++) s += sX[r][k]*sW[c][k];
        XL[(size_t)(r0+r)*64 + c] = s;
    }
    __syncthreads();
    for(int i=tid;i<4096;i+=256){ int rr=i>>6, c=i&63; sW[rr][c]=Wr[i]; }
    __syncthreads();
    #pragma unroll 4
    for(int cc=0; cc<16; cc++){
        int c = cq*16 + cc;
        float s = br[c];
        #pragma unroll
        for(int k=0;k<64;k++) s += sX[r][k]*sW[c][k];
        XR[(size_t)(r0+r)*64 + c] = s;
    }
}

// ---- GATv2 on dense 32x32 block graph; one warp per dst node; tanh output ----
__global__ void __launch_bounds__(128) k_gat(const float* __restrict__ XL,
                                             const float* __restrict__ XR,
                                             const float* __restrict__ att,
                                             const float* __restrict__ bias,
                                             float* __restrict__ OUT)
{
    int w = threadIdx.x >> 5, lane = threadIdx.x & 31;
    int g = blockIdx.x >> 3;
    int d = ((blockIdx.x & 7) << 2) + w;
    int nd = g*32 + d;
    float xr0 = XR[(size_t)nd*64 + lane];
    float xr1 = XR[(size_t)nd*64 + 32 + lane];
    float a0 = att[lane], a1 = att[lane+32];
    const float* xlg = XL + (size_t)g*32*64;
    float lg[32];
    #pragma unroll
    for(int s=0;s<32;s++){
        float u = xlg[s*64 + lane]      + xr0;
        float v = xlg[s*64 + 32 + lane] + xr1;
        u = u>0.f ? u : 0.2f*u;
        v = v>0.f ? v : 0.2f*v;
        float t = u*a0 + v*a1;
        #pragma unroll
        for(int o=16;o>0;o>>=1) t += __shfl_xor_sync(0xffffffffu, t, o);
        lg[s] = t;
    }
    float m = -1e30f;
    #pragma unroll
    for(int s=0;s<32;s++) m = fmaxf(m, lg[s]);
    float den = 0.f;
    #pragma unroll
    for(int s=0;s<32;s++){ lg[s] = expf(lg[s]-m); den += lg[s]; }
    float inv = 1.f/den, o0=0.f, o1=0.f;
    #pragma unroll
    for(int s=0;s<32;s++){
        float al = lg[s]*inv;
        o0 += al * xlg[s*64 + lane];
        o1 += al * xlg[s*64 + 32 + lane];
    }
    OUT[(size_t)nd*64 + lane]      = tanhf(o0 + bias[lane]);
    OUT[(size_t)nd*64 + 32 + lane] = tanhf(o1 + bias[lane+32]);
}

// ---- fusion concat ----
__global__ void k_fus(const float* __restrict__ XN, const float* __restrict__ G0,
                      const float* __restrict__ G1, float* __restrict__ FUS)
{
    int i = blockIdx.x*256 + threadIdx.x;  // 4096*128
    int n = i >> 7, q = i & 127;
    FUS[i] = (q < 64) ? XN[(size_t)n*64 + q]
                      : (G0[(size_t)n*64 + q-64] + G1[(size_t)n*64 + q-64]);
}

// ---- capsule routing (3 iters) + final head ----
__global__ void __launch_bounds__(64) k_route(const float* __restrict__ PR,
                                              const float* __restrict__ Fw,
                                              const float* __restrict__ Fb,
                                              float* __restrict__ out)
{
    int n = blockIdx.x, l = threadIdx.x;
    const float* base = PR + (size_t)n*65536 + l;   // idx: c*2048 + o*64
    float o0[32], o1[32], pc[32], te[32];
    #pragma unroll
    for(int o=0;o<32;o++) o0[o]=0.f;
    for(int c=0;c<32;c++){
        const float* pcol = base + (size_t)c*2048;
        #pragma unroll
        for(int o=0;o<32;o++) o0[o] += pcol[o*64];
    }
    #pragma unroll
    for(int o=0;o<32;o++){ o0[o] *= (1.f/32.f); o1[o]=0.f; }
    for(int c=0;c<32;c++){
        const float* pcol = base + (size_t)c*2048;
        float m = -1e30f;
        #pragma unroll
        for(int o=0;o<32;o++){ pc[o]=pcol[o*64]; float lgv = pc[o]*o0[o]; te[o]=lgv; m = fmaxf(m,lgv); }
        float den=0.f;
        #pragma unroll
        for(int o=0;o<32;o++){ te[o]=expf(te[o]-m); den+=te[o]; }
        float inv = 1.f/den;
        #pragma unroll
        for(int o=0;o<32;o++) o1[o] += te[o]*inv*pc[o];
    }
    #pragma unroll
    for(int o=0;o<32;o++){ o0[o] += o1[o]; o1[o]=0.f; }
    for(int c=0;c<32;c++){
        const float* pcol = base + (size_t)c*2048;
        float m = -1e30f;
        #pragma unroll
        for(int o=0;o<32;o++){ pc[o]=pcol[o*64]; float lgv = pc[o]*o0[o]; te[o]=lgv; m = fmaxf(m,lgv); }
        float den=0.f;
        #pragma unroll
        for(int o=0;o<32;o++){ te[o]=expf(te[o]-m); den+=te[o]; }
        float inv = 1.f/den;
        #pragma unroll
        for(int o=0;o<32;o++) o1[o] += te[o]*inv*pc[o];
    }
    __shared__ float sc[32][65];
    #pragma unroll
    for(int o=0;o<32;o++) sc[o][l] = tanhf(o1[o]);
    __syncthreads();
    for(int q=0;q<16;q++){
        int idx = l*16 + q;
        int o = idx >> 5, d2 = idx & 31;
        float s = Fb[d2];
        #pragma unroll
        for(int ll=0;ll<64;ll++) s += sc[o][ll]*Fw[d2*64+ll];
        out[(size_t)n*1024 + o*32 + d2] = tanhf(s);
    }
}

extern "C" void kernel_launch(void* const* d_in, const int* in_sizes, int n_in,
                              void* d_out, int out_size)
{
    const float* inputs = (const float*)d_in[0];
    const float* Wih0 = (const float*)d_in[1];
    const float* Whh0 = (const float*)d_in[2];
    const float* bih0 = (const float*)d_in[3];
    const float* bhh0 = (const float*)d_in[4];
    const float* Wih1 = (const float*)d_in[5];
    const float* Whh1 = (const float*)d_in[6];
    const float* bih1 = (const float*)d_in[7];
    const float* bhh1 = (const float*)d_in[8];
    const float* A_w  = (const float*)d_in[9];
    const float* A_b  = (const float*)d_in[10];
    const float* g0_Wl = (const float*)d_in[11];
    const float* g0_bl = (const float*)d_in[12];
    const float* g0_Wr = (const float*)d_in[13];
    const float* g0_br = (const float*)d_in[14];
    const float* g0_att = (const float*)d_in[15];
    const float* g0_bias = (const float*)d_in[16];
    const float* g1_Wl = (const float*)d_in[17];
    const float* g1_bl = (const float*)d_in[18];
    const float* g1_Wr = (const float*)d_in[19];
    const float* g1_br = (const float*)d_in[20];
    const float* g1_att = (const float*)d_in[21];
    const float* g1_bias = (const float*)d_in[22];
    const float* W_caps = (const float*)d_in[23];
    const float* F_w = (const float*)d_in[24];
    const float* F_b = (const float*)d_in[25];
    float* out = (float*)d_out;

    float *Gi,*H0,*Emb,*hz,*P,*XN,*XL,*XR,*G0,*G1,*FUS,*PR;
    __nv_bfloat16 *Xhi,*Xlo,*H0hi,*H0lo,*Ehi,*Elo,*hzb;
    __nv_bfloat16 *Wih0h,*Wih0l,*Whh0h,*Whh0l,*Wih1h,*Wih1l,*Whh1h,*Whh1l;
    cudaGetSymbolAddress((void**)&Gi,  g_Gi);
    cudaGetSymbolAddress((void**)&H0,  g_H0);
    cudaGetSymbolAddress((void**)&Emb, g_Emb);
    cudaGetSymbolAddress((void**)&hz,  g_hz);
    cudaGetSymbolAddress((void**)&P,   g_P);
    cudaGetSymbolAddress((void**)&XN,  g_XN);
    cudaGetSymbolAddress((void**)&XL,  g_XL);
    cudaGetSymbolAddress((void**)&XR,  g_XR);
    cudaGetSymbolAddress((void**)&G0,  g_G0);
    cudaGetSymbolAddress((void**)&G1,  g_G1);
    cudaGetSymbolAddress((void**)&FUS, g_FUS);
    cudaGetSymbolAddress((void**)&PR,  g_PR);
    cudaGetSymbolAddress((void**)&Xhi, g_Xhi);  cudaGetSymbolAddress((void**)&Xlo, g_Xlo);
    cudaGetSymbolAddress((void**)&H0hi,g_H0hi); cudaGetSymbolAddress((void**)&H0lo,g_H0lo);
    cudaGetSymbolAddress((void**)&Ehi, g_Ehi);  cudaGetSymbolAddress((void**)&Elo, g_Elo);
    cudaGetSymbolAddress((void**)&hzb, g_hzb);
    cudaGetSymbolAddress((void**)&Wih0h, g_Wih0h); cudaGetSymbolAddress((void**)&Wih0l, g_Wih0l);
    cudaGetSymbolAddress((void**)&Whh0h, g_Whh0h); cudaGetSymbolAddress((void**)&Whh0l, g_Whh0l);
    cudaGetSymbolAddress((void**)&Wih1h, g_Wih1h); cudaGetSymbolAddress((void**)&Wih1l, g_Wih1l);
    cudaGetSymbolAddress((void**)&Whh1h, g_Whh1h); cudaGetSymbolAddress((void**)&Whh1l, g_Whh1l);

    const int NTOT = Bc*Tc*Fc;           // 8.4M
    const int WTOT = G3*Fc;              // 12.58M
    k_zero<<<(Tc*Fc+255)/256, 256>>>(hz, Tc*Fc);
    k_zerob<<<(Tc*Fc+255)/256, 256>>>(hzb, Tc*Fc);
    k_sansplit4<<<(NTOT/4+255)/256, 256>>>((const float4*)inputs, (__nv_bfloat162*)Xhi, (__nv_bfloat162*)Xlo, NTOT/4);
    k_wsplit4<<<(WTOT/4+255)/256, 256>>>((const float4*)Wih0, (__nv_bfloat162*)Wih0h, (__nv_bfloat162*)Wih0l, WTOT/4);
    k_wsplit4<<<(WTOT/4+255)/256, 256>>>((const float4*)Whh0, (__nv_bfloat162*)Whh0h, (__nv_bfloat162*)Whh0l, WTOT/4);
    k_wsplit4<<<(WTOT/4+255)/256, 256>>>((const float4*)Wih1, (__nv_bfloat162*)Wih1h, (__nv_bfloat162*)Wih1l, WTOT/4);
    k_wsplit4<<<(WTOT/4+255)/256, 256>>>((const float4*)Whh1, (__nv_bfloat162*)Whh1h, (__nv_bfloat162*)Whh1l, WTOT/4);

    // layer 0: input-gate GEMM (full K, bias bih0) then recurrent scan
    k_mma<<<dim3(G3/128, (Bc*Tc)/32, 1), 128>>>(Xhi, Xlo, Wih0h, Wih0l, Gi, bih0, Fc, Fc, G3, 0);
    for(int b=0;b<Bc;b++){
        const __nv_bfloat16* ahi = b ? (H0hi + (size_t)(b-1)*Tc*Fc) : hzb;
        const __nv_bfloat16* alo = b ? (H0lo + (size_t)(b-1)*Tc*Fc) : hzb;
        const float* hp = b ? (H0 + (size_t)(b-1)*Tc*Fc) : hz;
        k_mma<<<dim3(G3/128, 1, KSPLIT), 128>>>(ahi, alo, Whh0h, Whh0l, P, nullptr, Fc, KCHUNK, G3, Tc*G3);
        k_gate<<<64, 256>>>(b, P, Gi, bhh0, hp, H0, H0hi, H0lo);
    }
    // layer 1
    k_mma<<<dim3(G3/128, (Bc*Tc)/32, 1), 128>>>(H0hi, H0lo, Wih1h, Wih1l, Gi, bih1, Fc, Fc, G3, 0);
    for(int b=0;b<Bc;b++){
        const __nv_bfloat16* ahi = b ? (Ehi + (size_t)(b-1)*Tc*Fc) : hzb;
        const __nv_bfloat16* alo = b ? (Elo + (size_t)(b-1)*Tc*Fc) : hzb;
        const float* hp = b ? (Emb + (size_t)(b-1)*Tc*Fc) : hz;
        k_mma<<<dim3(G3/128, 1, KSPLIT), 128>>>(ahi, alo, Whh1h, Whh1l, P, nullptr, Fc, KCHUNK, G3, Tc*G3);
        k_gate<<<64, 256>>>(b, P, Gi, bhh1, hp, Emb, Ehi, Elo);
    }
    // attention -> node features
    k_attn<<<(Bc*Fc)/256, 256>>>(Emb, A_w, A_b, XN);
    // GAT layer 0
    k_lin64<<<Nn/64, 256>>>(XN, g0_Wl, g0_bl, g0_Wr, g0_br, XL, XR);
    k_gat<<<1024, 128>>>(XL, XR, g0_att, g0_bias, G0);
    // GAT layer 1
    k_lin64<<<Nn/64, 256>>>(G0, g1_Wl, g1_bl, g1_Wr, g1_br, XL, XR);
    k_gat<<<1024, 128>>>(XL, XR, g1_att, g1_bias, G1);
    // fusion + capsule priors
    k_fus<<<(Nn*128)/256, 256>>>(XN, G0, G1, FUS);
    k_sgemm<<<dim3(2048/128, Nn/128), 256>>>(FUS, W_caps, nullptr, PR, 2048, 128);
    // routing + head
    k_route<<<Bc, 64>>>(PR, F_w, F_b, out);
}

// round 9
// speedup vs baseline: 1.7305x; 1.0541x over previous
#include <cuda_runtime.h>
#include <cuda_bf16.h>
#include <math.h>
#include <stdint.h>

#define Bc 128
#define Tc 32
#define Fc 2048
#define G3 6144
#define Hc 64
#define Nn 4096
#define KSPLIT 16        // P buffer sizing only
#define SCAN_KS 8
#define SCAN_KC 256      // Fc / SCAN_KS
#define NCTA 296         // 2 x 148, guaranteed co-resident at 2 CTAs/SM
#define SCAN_THREADS 256
#define NWARP (NCTA*8)   // 2368
#define NTASK (192*SCAN_KS) // 1536

// ---- static scratch (no cudaMalloc allowed) ----
__device__ float g_Gi[(size_t)Bc*Tc*G3];
__device__ float g_H0[Bc*Tc*Fc];
__device__ float g_Emb[Bc*Tc*Fc];
__device__ float g_hz[Tc*Fc];
__device__ float g_P[(size_t)KSPLIT*Tc*G3];
__device__ float g_XN[Nn*Hc];
__device__ float g_XL[Nn*Hc];
__device__ float g_XR[Nn*Hc];
__device__ float g_G0[Nn*Hc];
__device__ float g_G1[Nn*Hc];
__device__ float g_FUS[Nn*2*Hc];
__device__ float g_PR[(size_t)Nn*2048];

// bf16 hi/lo split buffers
__device__ __nv_bfloat16 g_Xhi[Bc*Tc*Fc],  g_Xlo[Bc*Tc*Fc];
__device__ __nv_bfloat16 g_H0hi[Bc*Tc*Fc], g_H0lo[Bc*Tc*Fc];
__device__ __nv_bfloat16 g_Ehi[Bc*Tc*Fc],  g_Elo[Bc*Tc*Fc];
__device__ __nv_bfloat16 g_hzb[Tc*Fc];
__device__ __nv_bfloat16 g_Wih0h[(size_t)G3*Fc], g_Wih0l[(size_t)G3*Fc];
__device__ __nv_bfloat16 g_Whh0h[(size_t)G3*Fc], g_Whh0l[(size_t)G3*Fc];
__device__ __nv_bfloat16 g_Wih1h[(size_t)G3*Fc], g_Wih1l[(size_t)G3*Fc];
__device__ __nv_bfloat16 g_Whh1h[(size_t)G3*Fc], g_Whh1l[(size_t)G3*Fc];

// grid-barrier state (self-consistent across launches: cnt returns to 0, gen monotonic)
__device__ unsigned int g_cnt = 0;
__device__ unsigned int g_gen = 0;

// ---- packed f32x2 helpers (capsule GEMM only) ----
__device__ __forceinline__ unsigned long long pk2(float x){
    unsigned long long r; asm("mov.b64 %0,{%1,%1};" : "=l"(r) : "f"(x)); return r;
}
__device__ __forceinline__ void ffma2(unsigned long long& d, unsigned long long a, unsigned long long b){
    asm("fma.rn.f32x2 %0,%1,%2,%0;" : "+l"(d) : "l"(a), "l"(b));
}
__device__ __forceinline__ float2 up2(unsigned long long v){
    float2 r; asm("mov.b64 {%0,%1},%2;" : "=f"(r.x), "=f"(r.y) : "l"(v)); return r;
}

// ---- bf16 mma.sync m16n8k16 ----
__device__ __forceinline__ void mma16816(float* c, uint32_t a0, uint32_t a1, uint32_t a2, uint32_t a3,
                                         uint32_t b0, uint32_t b1){
    asm volatile("mma.sync.aligned.m16n8k16.row.col.f32.bf16.bf16.f32 "
        "{%0,%1,%2,%3}, {%4,%5,%6,%7}, {%8,%9}, {%0,%1,%2,%3};"
        : "+f"(c[0]), "+f"(c[1]), "+f"(c[2]), "+f"(c[3])
        : "r"(a0), "r"(a1), "r"(a2), "r"(a3), "r"(b0), "r"(b1));
}
__device__ __forceinline__ uint32_t ld32(const __nv_bfloat16* p){ return *(const uint32_t*)p; }

// ---- utility ----
__global__ void k_zero(float* p, int n){ int i=blockIdx.x*256+threadIdx.x; if(i<n) p[i]=0.f; }
__global__ void k_zerob(__nv_bfloat16* p, int n){ int i=blockIdx.x*256+threadIdx.x; if(i<n) p[i]=__float2bfloat16(0.f); }

__device__ __forceinline__ void split1(float v, __nv_bfloat16& h, __nv_bfloat16& l){
    h = __float2bfloat16(v);
    l = __float2bfloat16(v - __bfloat162float(h));
}
__device__ __forceinline__ float san1(float v){
    if (isnan(v)) return 0.f;
    if (isinf(v)) return (v>0.f) ? 1.0f : -3.3e38f;
    return v;
}

__global__ void k_sansplit4(const float4* __restrict__ in, __nv_bfloat162* __restrict__ hi,
                            __nv_bfloat162* __restrict__ lo, int n4){
    int i = blockIdx.x*256 + threadIdx.x;
    if(i<n4){
        float4 v = in[i];
        v.x=san1(v.x); v.y=san1(v.y); v.z=san1(v.z); v.w=san1(v.w);
        __nv_bfloat16 h0,l0,h1,l1,h2,l2,h3,l3;
        split1(v.x,h0,l0); split1(v.y,h1,l1); split1(v.z,h2,l2); split1(v.w,h3,l3);
        __nv_bfloat162 a,b,c,d; a.x=h0;a.y=h1; b.x=h2;b.y=h3; c.x=l0;c.y=l1; d.x=l2;d.y=l3;
        hi[2*i]=a; hi[2*i+1]=b; lo[2*i]=c; lo[2*i+1]=d;
    }
}
__global__ void k_wsplit4(const float4* __restrict__ W, __nv_bfloat162* __restrict__ hi,
                          __nv_bfloat162* __restrict__ lo, int n4){
    int i = blockIdx.x*256 + threadIdx.x;
    if(i<n4){
        float4 v = W[i];
        __nv_bfloat16 h0,l0,h1,l1,h2,l2,h3,l3;
        split1(v.x,h0,l0); split1(v.y,h1,l1); split1(v.z,h2,l2); split1(v.w,h3,l3);
        __nv_bfloat162 a,b,c,d; a.x=h0;a.y=h1; b.x=h2;b.y=h3; c.x=l0;c.y=l1; d.x=l2;d.y=l3;
        hi[2*i]=a; hi[2*i+1]=b; lo[2*i]=c; lo[2*i+1]=d;
    }
}

// ---- split-bf16 tensor-core GEMM (input gates + any batched GEMM) ----
// grid (Ncols/128, M/32, ksplit), block 128 (4 warps x 32 cols). (R8, verified)
#define LOADK(I, KB) do{ \
    const __nv_bfloat16 *pa0 = Ahi + aoff + (KB); \
    const __nv_bfloat16 *qa0 = Alo + aoff + (KB); \
    const __nv_bfloat16 *pb0 = Bhi + boff + (KB); \
    const __nv_bfloat16 *qb0 = Blo + boff + (KB); \
    ah[I][0][0]=ld32(pa0);          ah[I][0][2]=ld32(pa0+8); \
    ah[I][0][1]=ld32(pa0+8*Ks);     ah[I][0][3]=ld32(pa0+8*Ks+8); \
    ah[I][1][0]=ld32(pa0+16*Ks);    ah[I][1][2]=ld32(pa0+16*Ks+8); \
    ah[I][1][1]=ld32(pa0+24*Ks);    ah[I][1][3]=ld32(pa0+24*Ks+8); \
    al[I][0][0]=ld32(qa0);          al[I][0][2]=ld32(qa0+8); \
    al[I][0][1]=ld32(qa0+8*Ks);     al[I][0][3]=ld32(qa0+8*Ks+8); \
    al[I][1][0]=ld32(qa0+16*Ks);    al[I][1][2]=ld32(qa0+16*Ks+8); \
    al[I][1][1]=ld32(qa0+24*Ks);    al[I][1][3]=ld32(qa0+24*Ks+8); \
    bh[I][0][0]=ld32(pb0);          bh[I][0][1]=ld32(pb0+8); \
    bh[I][1][0]=ld32(pb0+8*Ks);     bh[I][1][1]=ld32(pb0+8*Ks+8); \
    bh[I][2][0]=ld32(pb0+16*Ks);    bh[I][2][1]=ld32(pb0+16*Ks+8); \
    bh[I][3][0]=ld32(pb0+24*Ks);    bh[I][3][1]=ld32(pb0+24*Ks+8); \
    bl[I][0][0]=ld32(qb0);          bl[I][0][1]=ld32(qb0+8); \
    bl[I][1][0]=ld32(qb0+8*Ks);     bl[I][1][1]=ld32(qb0+8*Ks+8); \
    bl[I][2][0]=ld32(qb0+16*Ks);    bl[I][2][1]=ld32(qb0+16*Ks+8); \
    bl[I][3][0]=ld32(qb0+24*Ks);    bl[I][3][1]=ld32(qb0+24*Ks+8); \
}while(0)

#define MMAK(I) do{ \
    _Pragma("unroll") \
    for(int nt=0;nt<4;nt++){ \
        _Pragma("unroll") \
        for(int mt=0;mt<2;mt++){ \
            mma16816(acc[mt][nt], ah[I][mt][0],ah[I][mt][1],ah[I][mt][2],ah[I][mt][3], bh[I][nt][0], bh[I][nt][1]); \
            mma16816(acc[mt][nt], al[I][mt][0],al[I][mt][1],al[I][mt][2],al[I][mt][3], bh[I][nt][0], bh[I][nt][1]); \
            mma16816(acc[mt][nt], ah[I][mt][0],ah[I][mt][1],ah[I][mt][2],ah[I][mt][3], bl[I][nt][0], bl[I][nt][1]); \
        } \
    } \
}while(0)

__global__ void __launch_bounds__(128, 4) k_mma(const __nv_bfloat16* __restrict__ Ahi,
                                                const __nv_bfloat16* __restrict__ Alo,
                                                const __nv_bfloat16* __restrict__ Bhi,
                                                const __nv_bfloat16* __restrict__ Blo,
                                                float* __restrict__ Cout,
                                                const float* __restrict__ bias,
                                                int K, int kchunk, int Ncols, int sliceStride)
{
    const int lane = threadIdx.x & 31;
    const int warp = threadIdx.x >> 5;
    const int gid = lane >> 2, tq = lane & 3;
    const int m0 = blockIdx.y * 32;
    const int n0 = blockIdx.x * 128 + warp * 32;
    const int kb0 = blockIdx.z * kchunk;
    const size_t Ks = K;

    const size_t aoff = (size_t)(m0 + gid)*Ks + tq*2;
    const size_t boff = (size_t)(n0 + gid)*Ks + tq*2;

    float acc[2][4][4];
    #pragma unroll
    for(int mt=0;mt<2;mt++)
        #pragma unroll
        for(int nt=0;nt<4;nt++)
            #pragma unroll
            for(int q=0;q<4;q++) acc[mt][nt][q]=0.f;

    uint32_t ah[2][2][4], al[2][2][4], bh[2][4][2], bl[2][4][2];

    const int NT = kchunk >> 4;
    LOADK(0, kb0);
    #pragma unroll 1
    for(int t=0; t<NT; t+=2){
        if(t+1 < NT) LOADK(1, kb0 + (t+1)*16);
        MMAK(0);
        if(t+2 < NT) LOADK(0, kb0 + (t+2)*16);
        if(t+1 < NT) MMAK(1);
    }

    float* Cb = Cout + (size_t)blockIdx.z * sliceStride;
    #pragma unroll
    for(int mt=0;mt<2;mt++){
        #pragma unroll
        for(int nt=0;nt<4;nt++){
            int row = m0 + mt*16 + gid;
            int col = n0 + nt*8 + tq*2;
            float b0 = bias ? bias[col]   : 0.f;
            float b1 = bias ? bias[col+1] : 0.f;
            float2 v0 = {acc[mt][nt][0] + b0, acc[mt][nt][1] + b1};
            float2 v1 = {acc[mt][nt][2] + b0, acc[mt][nt][3] + b1};
            *(float2*)&Cb[(size_t)row*Ncols + col]     = v0;
            *(float2*)&Cb[(size_t)(row+8)*Ncols + col] = v1;
        }
    }
}

// ---- grid barrier for the persistent scan kernel ----
__device__ __forceinline__ void gbar(){
    __threadfence();                 // release this thread's writes
    __syncthreads();
    if(threadIdx.x==0){
        unsigned int gen = *((volatile unsigned int*)&g_gen);
        if(atomicAdd(&g_cnt, 1u) == NCTA-1u){
            g_cnt = 0;
            __threadfence();
            atomicAdd(&g_gen, 1u);
        } else {
            while(*((volatile unsigned int*)&g_gen) == gen) __nanosleep(40);
        }
        __threadfence();
    }
    __syncthreads();
}

// ---- persistent GRU scan: 128 steps of (recurrent GEMM -> gate) in ONE kernel ----
// grid NCTA=296 x 256 thr, launch_bounds(256,2): regs<=128, smem=0 -> all CTAs co-resident.
__global__ void __launch_bounds__(SCAN_THREADS, 2) k_scan(
    const __nv_bfloat16* __restrict__ Whi, const __nv_bfloat16* __restrict__ Wlo,
    const float* __restrict__ Gi, const float* __restrict__ bhh,
    const float* __restrict__ hz, const __nv_bfloat16* __restrict__ hzb,
    float* __restrict__ Hall, __nv_bfloat16* __restrict__ Hhi, __nv_bfloat16* __restrict__ Hlo,
    float* __restrict__ P)
{
    const int lane = threadIdx.x & 31;
    const int warp = threadIdx.x >> 5;
    const int gid = lane >> 2, tq = lane & 3;
    // spread tasks evenly: task = warp*NCTA + blockIdx.x
    const int task = warp*NCTA + blockIdx.x;
    const int tid  = blockIdx.x*SCAN_THREADS + threadIdx.x;
    const size_t Ks = Fc;

    int nt=0, ks=0, n0=0, kb0=0;
    size_t boff = 0;
    if(task < NTASK){
        nt = task % 192; ks = task / 192;
        n0 = nt*32; kb0 = ks*SCAN_KC;
        boff = (size_t)(n0 + gid)*Ks + tq*2;
    }
    const size_t aoff = (size_t)gid*Ks + tq*2;   // M=32, m0=0

    for(int b=0; b<Bc; b++){
        const __nv_bfloat16* Ahi = b ? (Hhi + (size_t)(b-1)*Tc*Fc) : hzb;
        const __nv_bfloat16* Alo = b ? (Hlo + (size_t)(b-1)*Tc*Fc) : hzb;

        // ---- GEMM phase: 32x32 tile per warp-task over SCAN_KC k ----
        if(task < NTASK){
            float acc[2][4][4];
            #pragma unroll
            for(int mt=0;mt<2;mt++)
                #pragma unroll
                for(int nn=0;nn<4;nn++)
                    #pragma unroll
                    for(int q=0;q<4;q++) acc[mt][nn][q]=0.f;

            uint32_t ah[2][4], al[2][4], bh[4][2], bl[4][2];
            #pragma unroll 1
            for(int kt=0; kt<SCAN_KC; kt+=16){
                const int kb = kb0 + kt;
                const __nv_bfloat16 *pa = Ahi + aoff + kb;
                const __nv_bfloat16 *qa = Alo + aoff + kb;
                const __nv_bfloat16 *pb = Whi + boff + kb;
                const __nv_bfloat16 *qb = Wlo + boff + kb;
                ah[0][0]=ld32(pa);        ah[0][2]=ld32(pa+8);
                ah[0][1]=ld32(pa+8*Ks);   ah[0][3]=ld32(pa+8*Ks+8);
                ah[1][0]=ld32(pa+16*Ks);  ah[1][2]=ld32(pa+16*Ks+8);
                ah[1][1]=ld32(pa+24*Ks);  ah[1][3]=ld32(pa+24*Ks+8);
                al[0][0]=ld32(qa);        al[0][2]=ld32(qa+8);
                al[0][1]=ld32(qa+8*Ks);   al[0][3]=ld32(qa+8*Ks+8);
                al[1][0]=ld32(qa+16*Ks);  al[1][2]=ld32(qa+16*Ks+8);
                al[1][1]=ld32(qa+24*Ks);  al[1][3]=ld32(qa+24*Ks+8);
                #pragma unroll
                for(int nn=0;nn<4;nn++){
                    bh[nn][0]=ld32(pb+(size_t)(nn*8)*Ks); bh[nn][1]=ld32(pb+(size_t)(nn*8)*Ks+8);
                    bl[nn][0]=ld32(qb+(size_t)(nn*8)*Ks); bl[nn][1]=ld32(qb+(size_t)(nn*8)*Ks+8);
                }
                #pragma unroll
                for(int nn=0;nn<4;nn++){
                    #pragma unroll
                    for(int mt=0;mt<2;mt++){
                        mma16816(acc[mt][nn], ah[mt][0],ah[mt][1],ah[mt][2],ah[mt][3], bh[nn][0], bh[nn][1]);
                        mma16816(acc[mt][nn], al[mt][0],al[mt][1],al[mt][2],al[mt][3], bh[nn][0], bh[nn][1]);
                        mma16816(acc[mt][nn], ah[mt][0],ah[mt][1],ah[mt][2],ah[mt][3], bl[nn][0], bl[nn][1]);
                    }
                }
            }
            float* Pb = P + (size_t)ks*Tc*G3;
            #pragma unroll
            for(int mt=0;mt<2;mt++){
                #pragma unroll
                for(int nn=0;nn<4;nn++){
                    int row = mt*16 + gid;
                    int col = n0 + nn*8 + tq*2;
                    float2 v0 = {acc[mt][nn][0], acc[mt][nn][1]};
                    float2 v1 = {acc[mt][nn][2], acc[mt][nn][3]};
                    *(float2*)&Pb[(size_t)row*G3 + col]     = v0;
                    *(float2*)&Pb[(size_t)(row+8)*G3 + col] = v1;
                }
            }
        }
        gbar();

        // ---- gate phase: 16384 quads ----
        if(tid < 16384){
            int row = tid >> 9, j = (tid & 511)*4;
            float4 gr = {0,0,0,0}, gz = {0,0,0,0}, gn = {0,0,0,0};
            #pragma unroll
            for(int s=0;s<SCAN_KS;s++){
                const float* p = P + ((size_t)s*Tc + row)*G3;
                float4 a  = __ldcg((const float4*)(p + j));
                float4 bv = __ldcg((const float4*)(p + 2048 + j));
                float4 c  = __ldcg((const float4*)(p + 4096 + j));
                gr.x+=a.x; gr.y+=a.y; gr.z+=a.z; gr.w+=a.w;
                gz.x+=bv.x; gz.y+=bv.y; gz.z+=bv.z; gz.w+=bv.w;
                gn.x+=c.x; gn.y+=c.y; gn.z+=c.z; gn.w+=c.w;
            }
            const float* gi = Gi + ((size_t)b*Tc + row)*G3;
            float4 gir = *(const float4*)(gi + j);
            float4 giz = *(const float4*)(gi + 2048 + j);
            float4 gin = *(const float4*)(gi + 4096 + j);
            float4 br = *(const float4*)(bhh + j);
            float4 bz = *(const float4*)(bhh + 2048 + j);
            float4 bn = *(const float4*)(bhh + 4096 + j);
            const float* hpp = b ? (Hall + (size_t)(b-1)*Tc*Fc) : hz;
            float4 hp = *(const float4*)(hpp + (size_t)row*Fc + j);
            float4 ho;
            {
                float r = 1.f/(1.f + expf(-(gir.x + gr.x + br.x)));
                float z = 1.f/(1.f + expf(-(giz.x + gz.x + bz.x)));
                float n = tanhf(gin.x + r*(gn.x + bn.x));
                ho.x = (1.f - z)*n + z*hp.x;
                r = 1.f/(1.f + expf(-(gir.y + gr.y + br.y)));
                z = 1.f/(1.f + expf(-(giz.y + gz.y + bz.y)));
                n = tanhf(gin.y + r*(gn.y + bn.y));
                ho.y = (1.f - z)*n + z*hp.y;
                r = 1.f/(1.f + expf(-(gir.z + gr.z + br.z)));
                z = 1.f/(1.f + expf(-(giz.z + gz.z + bz.z)));
                n = tanhf(gin.z + r*(gn.z + bn.z));
                ho.z = (1.f - z)*n + z*hp.z;
                r = 1.f/(1.f + expf(-(gir.w + gr.w + br.w)));
                z = 1.f/(1.f + expf(-(giz.w + gz.w + bz.w)));
                n = tanhf(gin.w + r*(gn.w + bn.w));
                ho.w = (1.f - z)*n + z*hp.w;
            }
            size_t base = ((size_t)b*Tc + row)*Fc + j;
            *(float4*)(Hall + base) = ho;
            __nv_bfloat16 h0,l0,h1,l1,h2,l2,h3,l3;
            split1(ho.x,h0,l0); split1(ho.y,h1,l1); split1(ho.z,h2,l2); split1(ho.w,h3,l3);
            __nv_bfloat162 hi01; hi01.x=h0; hi01.y=h1;
            __nv_bfloat162 hi23; hi23.x=h2; hi23.y=h3;
            __nv_bfloat162 lo01; lo01.x=l0; lo01.y=l1;
            __nv_bfloat162 lo23; lo23.x=l2; lo23.y=l3;
            *(__nv_bfloat162*)(Hhi + base)     = hi01;
            *(__nv_bfloat162*)(Hhi + base + 2) = hi23;
            *(__nv_bfloat162*)(Hlo + base)     = lo01;
            *(__nv_bfloat162*)(Hlo + base + 2) = lo23;
        }
        gbar();
    }
}

// ---- f32 SGEMM (capsule priors only) ----
__global__ void __launch_bounds__(256) k_sgemm(const float* __restrict__ A,
                                               const float* __restrict__ Bm,
                                               const float* __restrict__ bias,
                                               float* __restrict__ C,
                                               int Ncols, int K)
{
    __shared__ float As[8][128];
    __shared__ float Bs[8][128];
    const int tid = threadIdx.x;
    const int tx = tid & 15, ty = tid >> 4;
    const int m0 = blockIdx.y*128, n0 = blockIdx.x*128;
    const int lr = tid >> 1, lc = (tid & 1)*4;
    const float* Ap = A + (size_t)(m0+lr)*K + lc;
    const float* Bp = Bm + (size_t)(n0+lr)*K + lc;

    unsigned long long acc[8][4];
    #pragma unroll
    for(int i=0;i<8;i++)
        #pragma unroll
        for(int j=0;j<4;j++) acc[i][j]=0ULL;

    for(int k0=0;k0<K;k0+=8){
        float4 av = *(const float4*)(Ap + k0);
        float4 bv = *(const float4*)(Bp + k0);
        __syncthreads();
        As[lc+0][lr]=av.x; As[lc+1][lr]=av.y; As[lc+2][lr]=av.z; As[lc+3][lr]=av.w;
        Bs[lc+0][lr]=bv.x; Bs[lc+1][lr]=bv.y; Bs[lc+2][lr]=bv.z; Bs[lc+3][lr]=bv.w;
        __syncthreads();
        #pragma unroll
        for(int k=0;k<8;k++){
            float4 a0 = *(const float4*)&As[k][ty*8];
            float4 a1 = *(const float4*)&As[k][ty*8+4];
            ulonglong2 b01 = *(const ulonglong2*)&Bs[k][tx*8];
            ulonglong2 b23 = *(const ulonglong2*)&Bs[k][tx*8+4];
            unsigned long long aa[8];
            aa[0]=pk2(a0.x); aa[1]=pk2(a0.y); aa[2]=pk2(a0.z); aa[3]=pk2(a0.w);
            aa[4]=pk2(a1.x); aa[5]=pk2(a1.y); aa[6]=pk2(a1.z); aa[7]=pk2(a1.w);
            #pragma unroll
            for(int i=0;i<8;i++){
                ffma2(acc[i][0], aa[i], b01.x);
                ffma2(acc[i][1], aa[i], b01.y);
                ffma2(acc[i][2], aa[i], b23.x);
                ffma2(acc[i][3], aa[i], b23.y);
            }
        }
    }
    #pragma unroll
    for(int i=0;i<8;i++){
        int row = m0 + ty*8 + i;
        #pragma unroll
        for(int j=0;j<4;j++){
            float2 v = up2(acc[i][j]);
            int col = n0 + tx*8 + j*2;
            float b0 = bias ? bias[col]   : 0.f;
            float b1 = bias ? bias[col+1] : 0.f;
            C[(size_t)row*Ncols + col]   = v.x + b0;
            C[(size_t)row*Ncols + col+1] = v.y + b1;
        }
    }
}

// ---- temporal attention over T=32 per (b,f) ----
__global__ void __launch_bounds__(256) k_attn(const float* __restrict__ Emb,
                                              const float* __restrict__ Aw,
                                              const float* __restrict__ Ab,
                                              float* __restrict__ XN)
{
    __shared__ float sW[32][33];
    __shared__ float sB[32];
    int tid = threadIdx.x;
    for(int i=tid;i<1024;i+=256) sW[i>>5][i&31] = Aw[i];
    if(tid<32) sB[tid]=Ab[tid];
    __syncthreads();
    int g = blockIdx.x*256 + tid;
    int b = g >> 11, f = g & 2047;
    float tA[32];
    #pragma unroll
    for(int t=0;t<32;t++) tA[t] = tanhf(Emb[((size_t)b*32 + t)*Fc + f]);
    float mx = -1e30f, aw[32];
    #pragma unroll
    for(int t2=0;t2<32;t2++){
        float s = sB[t2];
        #pragma unroll
        for(int t=0;t<32;t++) s += tA[t]*sW[t2][t];
        aw[t2]=s; mx = fmaxf(mx, s);
    }
    float den=0.f, num=0.f;
    #pragma unroll
    for(int t=0;t<32;t++){ float e = expf(aw[t]-mx); den += e; num += e*tA[t]; }
    XN[g] = tanhf(num/den);
}

// ---- GAT projections ----
__global__ void __launch_bounds__(256) k_lin64(const float* __restrict__ X,
                                               const float* __restrict__ Wl, const float* __restrict__ bl,
                                               const float* __restrict__ Wr, const float* __restrict__ br,
                                               float* __restrict__ XL, float* __restrict__ XR)
{
    __shared__ float sX[64][65];
    __shared__ float sW[64][65];
    int tid = threadIdx.x;
    int r0 = blockIdx.x*64;
    for(int i=tid;i<4096;i+=256){ int r=i>>6, c=i&63; sX[r][c]=X[(size_t)(r0+r)*64+c]; }
    for(int i=tid;i<4096;i+=256){ int r=i>>6, c=i&63; sW[r][c]=Wl[i]; }
    __syncthreads();
    int r = tid & 63, cq = tid >> 6;
    #pragma unroll 4
    for(int cc=0; cc<16; cc++){
        int c = cq*16 + cc;
        float s = bl[c];
        #pragma unroll
        for(int k=0;k<64;k++) s += sX[r][k]*sW[c][k];
        XL[(size_t)(r0+r)*64 + c] = s;
    }
    __syncthreads();
    for(int i=tid;i<4096;i+=256){ int rr=i>>6, c=i&63; sW[rr][c]=Wr[i]; }
    __syncthreads();
    #pragma unroll 4
    for(int cc=0; cc<16; cc++){
        int c = cq*16 + cc;
        float s = br[c];
        #pragma unroll
        for(int k=0;k<64;k++) s += sX[r][k]*sW[c][k];
        XR[(size_t)(r0+r)*64 + c] = s;
    }
}

// ---- GATv2 dense 32x32 block graph ----
__global__ void __launch_bounds__(128) k_gat(const float* __restrict__ XL,
                                             const float* __restrict__ XR,
                                             const float* __restrict__ att,
                                             const float* __restrict__ bias,
                                             float* __restrict__ OUT)
{
    int w = threadIdx.x >> 5, lane = threadIdx.x & 31;
    int g = blockIdx.x >> 3;
    int d = ((blockIdx.x & 7) << 2) + w;
    int nd = g*32 + d;
    float xr0 = XR[(size_t)nd*64 + lane];
    float xr1 = XR[(size_t)nd*64 + 32 + lane];
    float a0 = att[lane], a1 = att[lane+32];
    const float* xlg = XL + (size_t)g*32*64;
    float lg[32];
    #pragma unroll
    for(int s=0;s<32;s++){
        float u = xlg[s*64 + lane]      + xr0;
        float v = xlg[s*64 + 32 + lane] + xr1;
        u = u>0.f ? u : 0.2f*u;
        v = v>0.f ? v : 0.2f*v;
        float t = u*a0 + v*a1;
        #pragma unroll
        for(int o=16;o>0;o>>=1) t += __shfl_xor_sync(0xffffffffu, t, o);
        lg[s] = t;
    }
    float m = -1e30f;
    #pragma unroll
    for(int s=0;s<32;s++) m = fmaxf(m, lg[s]);
    float den = 0.f;
    #pragma unroll
    for(int s=0;s<32;s++){ lg[s] = expf(lg[s]-m); den += lg[s]; }
    float inv = 1.f/den, o0=0.f, o1=0.f;
    #pragma unroll
    for(int s=0;s<32;s++){
        float al = lg[s]*inv;
        o0 += al * xlg[s*64 + lane];
        o1 += al * xlg[s*64 + 32 + lane];
    }
    OUT[(size_t)nd*64 + lane]      = tanhf(o0 + bias[lane]);
    OUT[(size_t)nd*64 + 32 + lane] = tanhf(o1 + bias[lane+32]);
}

// ---- fusion concat ----
__global__ void k_fus(const float* __restrict__ XN, const float* __restrict__ G0,
                      const float* __restrict__ G1, float* __restrict__ FUS)
{
    int i = blockIdx.x*256 + threadIdx.x;
    int n = i >> 7, q = i & 127;
    FUS[i] = (q < 64) ? XN[(size_t)n*64 + q]
                      : (G0[(size_t)n*64 + q-64] + G1[(size_t)n*64 + q-64]);
}

// ---- capsule routing + head ----
__global__ void __launch_bounds__(64) k_route(const float* __restrict__ PR,
                                              const float* __restrict__ Fw,
                                              const float* __restrict__ Fb,
                                              float* __restrict__ out)
{
    int n = blockIdx.x, l = threadIdx.x;
    const float* base = PR + (size_t)n*65536 + l;
    float o0[32], o1[32], pc[32], te[32];
    #pragma unroll
    for(int o=0;o<32;o++) o0[o]=0.f;
    for(int c=0;c<32;c++){
        const float* pcol = base + (size_t)c*2048;
        #pragma unroll
        for(int o=0;o<32;o++) o0[o] += pcol[o*64];
    }
    #pragma unroll
    for(int o=0;o<32;o++){ o0[o] *= (1.f/32.f); o1[o]=0.f; }
    for(int c=0;c<32;c++){
        const float* pcol = base + (size_t)c*2048;
        float m = -1e30f;
        #pragma unroll
        for(int o=0;o<32;o++){ pc[o]=pcol[o*64]; float lgv = pc[o]*o0[o]; te[o]=lgv; m = fmaxf(m,lgv); }
        float den=0.f;
        #pragma unroll
        for(int o=0;o<32;o++){ te[o]=expf(te[o]-m); den+=te[o]; }
        float inv = 1.f/den;
        #pragma unroll
        for(int o=0;o<32;o++) o1[o] += te[o]*inv*pc[o];
    }
    #pragma unroll
    for(int o=0;o<32;o++){ o0[o] += o1[o]; o1[o]=0.f; }
    for(int c=0;c<32;c++){
        const float* pcol = base + (size_t)c*2048;
        float m = -1e30f;
        #pragma unroll
        for(int o=0;o<32;o++){ pc[o]=pcol[o*64]; float lgv = pc[o]*o0[o]; te[o]=lgv; m = fmaxf(m,lgv); }
        float den=0.f;
        #pragma unroll
        for(int o=0;o<32;o++){ te[o]=expf(te[o]-m); den+=te[o]; }
        float inv = 1.f/den;
        #pragma unroll
        for(int o=0;o<32;o++) o1[o] += te[o]*inv*pc[o];
    }
    __shared__ float sc[32][65];
    #pragma unroll
    for(int o=0;o<32;o++) sc[o][l] = tanhf(o1[o]);
    __syncthreads();
    for(int q=0;q<16;q++){
        int idx = l*16 + q;
        int o = idx >> 5, d2 = idx & 31;
        float s = Fb[d2];
        #pragma unroll
        for(int ll=0;ll<64;ll++) s += sc[o][ll]*Fw[d2*64+ll];
        out[(size_t)n*1024 + o*32 + d2] = tanhf(s);
    }
}

extern "C" void kernel_launch(void* const* d_in, const int* in_sizes, int n_in,
                              void* d_out, int out_size)
{
    const float* inputs = (const float*)d_in[0];
    const float* Wih0 = (const float*)d_in[1];
    const float* Whh0 = (const float*)d_in[2];
    const float* bih0 = (const float*)d_in[3];
    const float* bhh0 = (const float*)d_in[4];
    const float* Wih1 = (const float*)d_in[5];
    const float* Whh1 = (const float*)d_in[6];
    const float* bih1 = (const float*)d_in[7];
    const float* bhh1 = (const float*)d_in[8];
    const float* A_w  = (const float*)d_in[9];
    const float* A_b  = (const float*)d_in[10];
    const float* g0_Wl = (const float*)d_in[11];
    const float* g0_bl = (const float*)d_in[12];
    const float* g0_Wr = (const float*)d_in[13];
    const float* g0_br = (const float*)d_in[14];
    const float* g0_att = (const float*)d_in[15];
    const float* g0_bias = (const float*)d_in[16];
    const float* g1_Wl = (const float*)d_in[17];
    const float* g1_bl = (const float*)d_in[18];
    const float* g1_Wr = (const float*)d_in[19];
    const float* g1_br = (const float*)d_in[20];
    const float* g1_att = (const float*)d_in[21];
    const float* g1_bias = (const float*)d_in[22];
    const float* W_caps = (const float*)d_in[23];
    const float* F_w = (const float*)d_in[24];
    const float* F_b = (const float*)d_in[25];
    float* out = (float*)d_out;

    float *Gi,*H0,*Emb,*hz,*P,*XN,*XL,*XR,*G0,*G1,*FUS,*PR;
    __nv_bfloat16 *Xhi,*Xlo,*H0hi,*H0lo,*Ehi,*Elo,*hzb;
    __nv_bfloat16 *Wih0h,*Wih0l,*Whh0h,*Whh0l,*Wih1h,*Wih1l,*Whh1h,*Whh1l;
    cudaGetSymbolAddress((void**)&Gi,  g_Gi);
    cudaGetSymbolAddress((void**)&H0,  g_H0);
    cudaGetSymbolAddress((void**)&Emb, g_Emb);
    cudaGetSymbolAddress((void**)&hz,  g_hz);
    cudaGetSymbolAddress((void**)&P,   g_P);
    cudaGetSymbolAddress((void**)&XN,  g_XN);
    cudaGetSymbolAddress((void**)&XL,  g_XL);
    cudaGetSymbolAddress((void**)&XR,  g_XR);
    cudaGetSymbolAddress((void**)&G0,  g_G0);
    cudaGetSymbolAddress((void**)&G1,  g_G1);
    cudaGetSymbolAddress((void**)&FUS, g_FUS);
    cudaGetSymbolAddress((void**)&PR,  g_PR);
    cudaGetSymbolAddress((void**)&Xhi, g_Xhi);  cudaGetSymbolAddress((void**)&Xlo, g_Xlo);
    cudaGetSymbolAddress((void**)&H0hi,g_H0hi); cudaGetSymbolAddress((void**)&H0lo,g_H0lo);
    cudaGetSymbolAddress((void**)&Ehi, g_Ehi);  cudaGetSymbolAddress((void**)&Elo, g_Elo);
    cudaGetSymbolAddress((void**)&hzb, g_hzb);
    cudaGetSymbolAddress((void**)&Wih0h, g_Wih0h); cudaGetSymbolAddress((void**)&Wih0l, g_Wih0l);
    cudaGetSymbolAddress((void**)&Whh0h, g_Whh0h); cudaGetSymbolAddress((void**)&Whh0l, g_Whh0l);
    cudaGetSymbolAddress((void**)&Wih1h, g_Wih1h); cudaGetSymbolAddress((void**)&Wih1l, g_Wih1l);
    cudaGetSymbolAddress((void**)&Whh1h, g_Whh1h); cudaGetSymbolAddress((void**)&Whh1l, g_Whh1l);

    const int NTOT = Bc*Tc*Fc;
    const int WTOT = G3*Fc;
    k_zero<<<(Tc*Fc+255)/256, 256>>>(hz, Tc*Fc);
    k_zerob<<<(Tc*Fc+255)/256, 256>>>(hzb, Tc*Fc);
    k_sansplit4<<<(NTOT/4+255)/256, 256>>>((const float4*)inputs, (__nv_bfloat162*)Xhi, (__nv_bfloat162*)Xlo, NTOT/4);
    k_wsplit4<<<(WTOT/4+255)/256, 256>>>((const float4*)Wih0, (__nv_bfloat162*)Wih0h, (__nv_bfloat162*)Wih0l, WTOT/4);
    k_wsplit4<<<(WTOT/4+255)/256, 256>>>((const float4*)Whh0, (__nv_bfloat162*)Whh0h, (__nv_bfloat162*)Whh0l, WTOT/4);
    k_wsplit4<<<(WTOT/4+255)/256, 256>>>((const float4*)Wih1, (__nv_bfloat162*)Wih1h, (__nv_bfloat162*)Wih1l, WTOT/4);
    k_wsplit4<<<(WTOT/4+255)/256, 256>>>((const float4*)Whh1, (__nv_bfloat162*)Whh1h, (__nv_bfloat162*)Whh1l, WTOT/4);

    // layer 0: input-gate GEMM then persistent scan
    k_mma<<<dim3(G3/128, (Bc*Tc)/32, 1), 128>>>(Xhi, Xlo, Wih0h, Wih0l, Gi, bih0, Fc, Fc, G3, 0);
    k_scan<<<NCTA, SCAN_THREADS>>>(Whh0h, Whh0l, Gi, bhh0, hz, hzb, H0, H0hi, H0lo, P);
    // layer 1
    k_mma<<<dim3(G3/128, (Bc*Tc)/32, 1), 128>>>(H0hi, H0lo, Wih1h, Wih1l, Gi, bih1, Fc, Fc, G3, 0);
    k_scan<<<NCTA, SCAN_THREADS>>>(Whh1h, Whh1l, Gi, bhh1, hz, hzb, Emb, Ehi, Elo, P);
    // attention -> node features
    k_attn<<<(Bc*Fc)/256, 256>>>(Emb, A_w, A_b, XN);
    // GAT layers
    k_lin64<<<Nn/64, 256>>>(XN, g0_Wl, g0_bl, g0_Wr, g0_br, XL, XR);
    k_gat<<<1024, 128>>>(XL, XR, g0_att, g0_bias, G0);
    k_lin64<<<Nn/64, 256>>>(G0, g1_Wl, g1_bl, g1_Wr, g1_br, XL, XR);
    k_gat<<<1024, 128>>>(XL, XR, g1_att, g1_bias, G1);
    // fusion + capsule priors
    k_fus<<<(Nn*128)/256, 256>>>(XN, G0, G1, FUS);
    k_sgemm<<<dim3(2048/128, Nn/128), 256>>>(FUS, W_caps, nullptr, PR, 2048, 128);
    // routing + head
    k_route<<<Bc, 64>>>(PR, F_w, F_b, out);
}